// round 15
// baseline (speedup 1.0000x reference)
#include <cuda_runtime.h>
#include <cuda_fp16.h>
#include <cstdint>
#include <cstddef>

// ---------------- problem constants ----------------
#define BB   1024
#define SS   10
#define NN   36
#define FF   2048
#define DD   2176
#define HH   2176
#define MROW (BB*SS)          // 10240
#define PROW (BB*NN)          // 36864
#define KCAT 4224             // DD + FF
#define KV   4352
#define KV2  (KV/2)

#define SZ_QKV (2176*2176)
#define SZ_W1  (2176*2048)
#define SZ_W2  (2048*2176)
#define SZ_W5  ((size_t)3*SZ_QKV + SZ_W1 + SZ_W2)
#define SZ_RZ  ((size_t)4096*KCAT)
#define SZ_NIH ((size_t)2048*DD)
#define SZ_NHH ((size_t)2048*FF)

// ---------------- scratch (device globals; no allocation allowed) --------
__device__ __half g_pano_ln[(size_t)PROW * DD];
__device__ __half g_kv     [(size_t)PROW * KV];
__device__ __half g_s      [(size_t)MROW * DD];
__device__ __half g_q      [(size_t)MROW * DD];
__device__ __half g_a      [(size_t)MROW * KCAT];   // [upd | hr]
__device__ __half g_t1     [(size_t)MROW * HH];
__device__ __half g_rz     [(size_t)MROW * 4096];
__device__ __half g_inn    [(size_t)MROW * FF];
__device__ __half g_hn     [(size_t)MROW * FF];
__device__ float  g_h      [(size_t)MROW * FF];
__device__ float  g_hnew   [(size_t)MROW * FF];
__device__ __half g_pre    [(size_t)MROW * FF];
__device__ __half g_wh     [SZ_W5];
__device__ __half g_wih    [SZ_NIH];     // W_ih rows 4096:6144
__device__ __half g_whh    [SZ_NHH];     // W_hh rows 4096:6144
__device__ __half g_wrz    [SZ_RZ];
__device__ float  g_brz    [4096];
__device__ float  g_bkv    [KV];
__device__ int            g_mask_mode;
__device__ unsigned char  g_mask[MROW];

// ---------------- helpers ----------------
__device__ __forceinline__ void cp16(void* dst, const void* src) {
    uint32_t d = (uint32_t)__cvta_generic_to_shared(dst);
    asm volatile("cp.async.cg.shared.global [%0], [%1], 16;" :: "r"(d), "l"(src));
}

__device__ __forceinline__ uint32_t smem_u32(const void* p) {
    uint32_t a;
    asm("{ .reg .u64 t; cvta.to.shared.u64 t, %1; cvt.u32.u64 %0, t; }" : "=r"(a) : "l"(p));
    return a;
}

__device__ __forceinline__ void ldsm4(uint32_t& d0, uint32_t& d1, uint32_t& d2,
                                      uint32_t& d3, uint32_t addr) {
    asm volatile("ldmatrix.sync.aligned.m8n8.x4.shared.b16 {%0,%1,%2,%3}, [%4];"
                 : "=r"(d0), "=r"(d1), "=r"(d2), "=r"(d3) : "r"(addr));
}

// =====================================================================
// Mask dtype detection + normalization.
// =====================================================================
__global__ void detect_mask(const unsigned char* __restrict__ m)
{
    __shared__ int has1, has23;
    if (threadIdx.x == 0) { has1 = 0; has23 = 0; }
    __syncthreads();
    for (int i = threadIdx.x; i < MROW; i += 256) {
        if (m[i]) {
            const int p = i & 3;
            if (p == 1) atomicOr(&has1, 1);
            if (p >= 2) atomicOr(&has23, 1);
        }
    }
    __syncthreads();
    if (threadIdx.x == 0)
        g_mask_mode = has1 ? 1 : (has23 ? 2 : 0);
}

__global__ void normalize_mask(const void* __restrict__ m)
{
    const int i = blockIdx.x * 256 + threadIdx.x;
    if (i >= MROW) return;
    const int mode = g_mask_mode;
    unsigned char r;
    if (mode == 1)      r = (((const unsigned char*)m)[i] != 0);
    else if (mode == 2) r = (((const float*)m)[i] != 0.0f);
    else                r = (((const int*)m)[i] != 0);
    g_mask[i] = r;
}

// ---------------- fused fp16 weight copies ----------------
__global__ void __launch_bounds__(256)
half_copy_all(const float* s0, const float* s1, const float* s2,
              const float* s3, const float* s4, __half* __restrict__ d)
{
    const size_t seg_end[5] = {
        (size_t)SZ_QKV, (size_t)2*SZ_QKV, (size_t)3*SZ_QKV,
        (size_t)3*SZ_QKV + SZ_W1, SZ_W5 };
    const float* srcs[5] = { s0, s1, s2, s3, s4 };

    const size_t i4 = (size_t)blockIdx.x * 256 + threadIdx.x;
    const size_t e0 = i4 * 4;
    if (e0 >= SZ_W5) return;

    int seg = 0;
    size_t base = 0;
#pragma unroll
    for (int k = 0; k < 5; k++) {
        if (e0 >= seg_end[k]) { seg = k + 1; base = seg_end[k]; }
    }
    const float4 v = *(const float4*)(srcs[seg] + (e0 - base));
    __half2 h0 = __floats2half2_rn(v.x, v.y);
    __half2 h1 = __floats2half2_rn(v.z, v.w);
    uint2 o; o.x = *(uint32_t*)&h0; o.y = *(uint32_t*)&h1;
    *(uint2*)(d + e0) = o;
}

__global__ void __launch_bounds__(256)
half_copy1(const float* __restrict__ s, __half* __restrict__ d, size_t n4)
{
    const size_t i = (size_t)blockIdx.x * 256 + threadIdx.x;
    if (i >= n4) return;
    const float4 v = ((const float4*)s)[i];
    __half2 h0 = __floats2half2_rn(v.x, v.y);
    __half2 h1 = __floats2half2_rn(v.z, v.w);
    uint2 o; o.x = *(uint32_t*)&h0; o.y = *(uint32_t*)&h1;
    ((uint2*)d)[i] = o;
}

// W_rz[o, 0:2176] = W_ih[o,:]; W_rz[o, 2176:4224] = W_hh[o,:]  (o < 4096)
__global__ void __launch_bounds__(256)
interleave_rz(const float* __restrict__ Wih, const float* __restrict__ Whh,
              __half* __restrict__ d)
{
    const size_t i4 = (size_t)blockIdx.x * 256 + threadIdx.x;
    const size_t e0 = i4 * 4;
    if (e0 >= SZ_RZ) return;
    const int o = (int)(e0 / KCAT);
    const int c = (int)(e0 % KCAT);
    const float* src = (c < DD) ? (Wih + (size_t)o * DD + c)
                                : (Whh + (size_t)o * FF + (c - DD));
    const float4 v = *(const float4*)src;
    __half2 h0 = __floats2half2_rn(v.x, v.y);
    __half2 h1 = __floats2half2_rn(v.z, v.w);
    uint2 ov; ov.x = *(uint32_t*)&h0; ov.y = *(uint32_t*)&h1;
    *(uint2*)(d + e0) = ov;
}

__global__ void __launch_bounds__(256)
bias_setup(const float* __restrict__ bih, const float* __restrict__ bhh,
           const float* __restrict__ bk, const float* __restrict__ bv,
           float* __restrict__ brz, float* __restrict__ bkv)
{
    const int i = blockIdx.x * 256 + threadIdx.x;
    if (i < 4096) brz[i] = bih[i] + bhh[i];
    if (i < KV)   bkv[i] = (i < DD) ? bk[i] : bv[i - DD];
}

// =====================================================================
// FP16 GEMM core (device body): CTA 128x128, 128 thr, 3-stage k64 ring.
// mode 0: Cf(f32,ldC)=acc+bias ; 1: Ch=relu ; 2: Cf=+addm & Ch ; 3: Ch
// =====================================================================
#define STG_BYTES 32768
#define GEMM_DSMEM (3*STG_BYTES + 1024)

__device__ __forceinline__ void load_stage(const __half* __restrict__ A, int ldA,
                                           const __half* __restrict__ W,
                                           int K, int bm0, int bn0, int kt,
                                           char* stg, int tid)
{
    const __half* Asrc = A + (size_t)bm0 * ldA + kt * 64;
    const __half* Wsrc = W + (size_t)bn0 * K + kt * 64;
#pragma unroll
    for (int i = 0; i < 8; i++) {
        const int idx = i * 128 + tid;
        const int row = idx >> 3;
        const int g   = idx & 7;
        const int perm = g ^ (row & 7);
        cp16(stg + row * 128 + perm * 16, Asrc + (size_t)row * ldA + g * 8);
    }
#pragma unroll
    for (int i = 0; i < 8; i++) {
        const int idx = i * 128 + tid;
        const int row = idx >> 3;
        const int g   = idx & 7;
        const int perm = g ^ (row & 7);
        cp16(stg + 16384 + row * 128 + perm * 16, Wsrc + (size_t)row * K + g * 8);
    }
    asm volatile("cp.async.commit_group;" ::: "memory");
}

__device__ __forceinline__ void load_frags(uint32_t stg, const uint32_t* oA,
                                           const uint32_t* oB,
                                           uint32_t a[4][4], uint32_t b[8][2])
{
#pragma unroll
    for (int mi = 0; mi < 4; mi++)
        ldsm4(a[mi][0], a[mi][1], a[mi][2], a[mi][3], stg + oA[mi]);
#pragma unroll
    for (int p = 0; p < 4; p++) {
        uint32_t d0, d1, d2, d3;
        ldsm4(d0, d1, d2, d3, stg + oB[p]);
        b[2 * p][0] = d0;     b[2 * p][1] = d2;
        b[2 * p + 1][0] = d1; b[2 * p + 1][1] = d3;
    }
}

__device__ __forceinline__ void do_mmas(const uint32_t a[4][4], const uint32_t b[8][2],
                                        float acc[4][8][4])
{
#pragma unroll
    for (int nj = 0; nj < 8; nj++) {
#pragma unroll
        for (int mi = 0; mi < 4; mi++) {
            asm volatile(
                "mma.sync.aligned.m16n8k16.row.col.f32.f16.f16.f32 "
                "{%0,%1,%2,%3},{%4,%5,%6,%7},{%8,%9},{%0,%1,%2,%3};\n"
                : "+f"(acc[mi][nj][0]), "+f"(acc[mi][nj][1]),
                  "+f"(acc[mi][nj][2]), "+f"(acc[mi][nj][3])
                : "r"(a[mi][0]), "r"(a[mi][1]), "r"(a[mi][2]), "r"(a[mi][3]),
                  "r"(b[nj][0]), "r"(b[nj][1]));
        }
    }
}

__device__ __forceinline__ void gemm_body(
    const __half* __restrict__ A, const __half* __restrict__ W,
    const float* __restrict__ bias, const float* __restrict__ addm,
    float* __restrict__ Cf, __half* __restrict__ Ch,
    int N, int K, int ldA, int ldC, int ldH, int mode)
{
    extern __shared__ char smraw[];
    char* base = (char*)(((uintptr_t)smraw + 1023) & ~(uintptr_t)1023);
    const uint32_t sb = smem_u32(base);

    const int tid  = threadIdx.x;
    const int lane = tid & 31;
    const int warp = tid >> 5;
    const int wm   = warp >> 1;
    const int wn   = warp & 1;
    const int gid  = lane >> 2;
    const int tg   = lane & 3;
    const int mtx  = lane >> 3;
    const int rowin = lane & 7;

    const int bm0 = blockIdx.y * 128;
    const int bn0 = blockIdx.x * 128;

    uint32_t offA[4][4], offB[4][4];
#pragma unroll
    for (int ks = 0; ks < 4; ks++) {
#pragma unroll
        for (int mi = 0; mi < 4; mi++) {
            const int r = wm * 64 + mi * 16 + (mtx & 1) * 8 + rowin;
            const int g = ks * 2 + (mtx >> 1);
            offA[ks][mi] = (uint32_t)(r * 128 + ((g ^ (r & 7)) << 4));
        }
#pragma unroll
        for (int p = 0; p < 4; p++) {
            const int r = wn * 64 + p * 16 + (mtx & 1) * 8 + rowin;
            const int g = ks * 2 + (mtx >> 1);
            offB[ks][p] = (uint32_t)(16384 + r * 128 + ((g ^ (r & 7)) << 4));
        }
    }

    float acc[4][8][4];
#pragma unroll
    for (int mi = 0; mi < 4; mi++)
#pragma unroll
        for (int nj = 0; nj < 8; nj++)
#pragma unroll
            for (int c = 0; c < 4; c++) acc[mi][nj][c] = 0.f;

    const int nkt = K >> 6;

    load_stage(A, ldA, W, K, bm0, bn0, 0, base,             tid);
    load_stage(A, ldA, W, K, bm0, bn0, 1, base + STG_BYTES, tid);
    asm volatile("cp.async.wait_group 1;" ::: "memory");
    __syncthreads();

    uint32_t fa[2][4][4], fb[2][8][2];
    load_frags(sb, offA[0], offB[0], fa[0], fb[0]);

    int stg_i = 0;
    for (int kt = 0; kt < nkt; kt++) {
        const uint32_t stg = sb + (uint32_t)stg_i * STG_BYTES;
        const int stg_n = (stg_i == 2) ? 0 : stg_i + 1;

        if (kt + 2 < nkt) {
            const int stg_p = (stg_n == 2) ? 0 : stg_n + 1;
            load_stage(A, ldA, W, K, bm0, bn0, kt + 2, base + stg_p * STG_BYTES, tid);
        } else {
            asm volatile("cp.async.commit_group;" ::: "memory");
        }
        load_frags(stg, offA[1], offB[1], fa[1], fb[1]);
        do_mmas(fa[0], fb[0], acc);

        load_frags(stg, offA[2], offB[2], fa[0], fb[0]);
        do_mmas(fa[1], fb[1], acc);

        load_frags(stg, offA[3], offB[3], fa[1], fb[1]);
        do_mmas(fa[0], fb[0], acc);

        asm volatile("cp.async.wait_group 1;" ::: "memory");
        __syncthreads();
        if (kt + 1 < nkt)
            load_frags(sb + (uint32_t)stg_n * STG_BYTES, offA[0], offB[0], fa[0], fb[0]);
        do_mmas(fa[1], fb[1], acc);

        stg_i = stg_n;
    }

    // epilogue
#pragma unroll
    for (int mi = 0; mi < 4; mi++) {
#pragma unroll
        for (int nj = 0; nj < 8; nj++) {
            const int col = bn0 + wn * 64 + nj * 8 + tg * 2;
            const float2 bv = *(const float2*)&bias[col];
#pragma unroll
            for (int ch = 0; ch < 2; ch++) {
                const int row = bm0 + wm * 64 + mi * 16 + gid + ch * 8;
                float x0 = acc[mi][nj][ch * 2 + 0] + bv.x;
                float x1 = acc[mi][nj][ch * 2 + 1] + bv.y;
                if (mode == 0) {
                    float2 o; o.x = x0; o.y = x1;
                    *(float2*)&Cf[(size_t)row * ldC + col] = o;
                } else if (mode == 1) {
                    __half2 hh = __floats2half2_rn(fmaxf(x0, 0.f), fmaxf(x1, 0.f));
                    *(__half2*)&Ch[(size_t)row * ldH + col] = hh;
                } else if (mode == 2) {
                    const float2 av = *(const float2*)&addm[(size_t)row * N + col];
                    x0 += av.x; x1 += av.y;
                    float2 o; o.x = x0; o.y = x1;
                    *(float2*)&Cf[(size_t)row * ldC + col] = o;
                    __half2 hh = __floats2half2_rn(x0, x1);
                    *(__half2*)&Ch[(size_t)row * ldH + col] = hh;
                } else {
                    __half2 hh = __floats2half2_rn(x0, x1);
                    *(__half2*)&Ch[(size_t)row * ldH + col] = hh;
                }
            }
        }
    }
}

__global__ void __launch_bounds__(128, 2)
gemm_fp16(const __half* __restrict__ A, const __half* __restrict__ W,
          const float* __restrict__ bias, const float* __restrict__ addm,
          float* __restrict__ Cf, __half* __restrict__ Ch,
          int M, int N, int K, int ldA, int ldC, int ldH, int mode)
{
    gemm_body(A, W, bias, addm, Cf, Ch, N, K, ldA, ldC, ldH, mode);
}

// Fused gate GEMMs: z=0 -> rz (N=4096,K=4224); z=1 -> inn; z=2 -> hn.
__global__ void __launch_bounds__(128, 2)
gemm_gates(const __half* __restrict__ acat,
           const __half* __restrict__ wrz, const float* __restrict__ brz,
           const __half* __restrict__ wih_n, const float* __restrict__ bih_n,
           const __half* __restrict__ whh_n, const float* __restrict__ bhh_n,
           __half* __restrict__ rz, __half* __restrict__ inn, __half* __restrict__ hn)
{
    const int z = blockIdx.z;
    if (z == 0) {
        gemm_body(acat, wrz, brz, nullptr, nullptr, rz, 4096, KCAT, KCAT, 0, 4096, 3);
    } else if (z == 1) {
        if (blockIdx.x >= 16) return;
        gemm_body(acat, wih_n, bih_n, nullptr, nullptr, inn, FF, DD, KCAT, 0, FF, 3);
    } else {
        if (blockIdx.x >= 16) return;
        gemm_body(acat + DD, whh_n, bhh_n, nullptr, nullptr, hn, FF, FF, KCAT, 0, FF, 3);
    }
}

// =====================================================================
// Row LayerNorm over first 2048 cols + optional tail passthrough.
// =====================================================================
__global__ void __launch_bounds__(256)
ln_rows(const float* __restrict__ in, __half* __restrict__ out,
        const float* __restrict__ g, const float* __restrict__ b,
        const float* __restrict__ tail_src,
        int in_stride, int out_stride, int tail_stride, int tail_len)
{
    const int row = blockIdx.x;
    const int tid = threadIdx.x;
    const float* x = in + (size_t)row * in_stride;

    const float4 va = *(const float4*)&x[tid * 4];
    const float4 vb = *(const float4*)&x[(tid + 256) * 4];

    float s  = (va.x + va.y) + (va.z + va.w) + (vb.x + vb.y) + (vb.z + vb.w);
    float ss = (va.x * va.x + va.y * va.y) + (va.z * va.z + va.w * va.w)
             + (vb.x * vb.x + vb.y * vb.y) + (vb.z * vb.z + vb.w * vb.w);

#pragma unroll
    for (int off = 16; off; off >>= 1) {
        s  += __shfl_down_sync(0xffffffffu, s, off);
        ss += __shfl_down_sync(0xffffffffu, ss, off);
    }
    __shared__ float rs[8], rss[8];
    __shared__ float s_mean, s_rstd;
    const int warp = tid >> 5, lane = tid & 31;
    if (lane == 0) { rs[warp] = s; rss[warp] = ss; }
    __syncthreads();
    if (warp == 0) {
        float S  = (lane < 8) ? rs[lane]  : 0.f;
        float SQ = (lane < 8) ? rss[lane] : 0.f;
#pragma unroll
        for (int off = 4; off; off >>= 1) {
            S  += __shfl_down_sync(0xffffffffu, S, off);
            SQ += __shfl_down_sync(0xffffffffu, SQ, off);
        }
        if (lane == 0) {
            const float mean = S * (1.f / 2048.f);
            const float var  = SQ * (1.f / 2048.f) - mean * mean;
            s_mean = mean;
            s_rstd = rsqrtf(var + 1e-5f);
        }
    }
    __syncthreads();
    const float mean = s_mean, rstd = s_rstd;

    __half* o = out + (size_t)row * out_stride;
    {
        const int c0 = tid * 4;
        const float4 g4 = *(const float4*)&g[c0];
        const float4 b4 = *(const float4*)&b[c0];
        __half2 h0 = __floats2half2_rn((va.x - mean) * rstd * g4.x + b4.x,
                                       (va.y - mean) * rstd * g4.y + b4.y);
        __half2 h1 = __floats2half2_rn((va.z - mean) * rstd * g4.z + b4.z,
                                       (va.w - mean) * rstd * g4.w + b4.w);
        *(__half2*)&o[c0]     = h0;
        *(__half2*)&o[c0 + 2] = h1;
    }
    {
        const int c1 = (tid + 256) * 4;
        const float4 g4 = *(const float4*)&g[c1];
        const float4 b4 = *(const float4*)&b[c1];
        __half2 h0 = __floats2half2_rn((vb.x - mean) * rstd * g4.x + b4.x,
                                       (vb.y - mean) * rstd * g4.y + b4.y);
        __half2 h1 = __floats2half2_rn((vb.z - mean) * rstd * g4.z + b4.z,
                                       (vb.w - mean) * rstd * g4.w + b4.w);
        *(__half2*)&o[c1]     = h0;
        *(__half2*)&o[c1 + 2] = h1;
    }
    if (tail_len) {
        for (int c = tid; c < tail_len; c += 256)
            o[2048 + c] = __float2half_rn(tail_src[(size_t)row * tail_stride + 2048 + c]);
    }
}

// =====================================================================
// Fused GRU + LayerNorm(pre): one CTA per row. Gates fp16.
// =====================================================================
__global__ void __launch_bounds__(256)
gru_ln(const __half* __restrict__ rz, const __half* __restrict__ inn,
       const __half* __restrict__ hn, const float* __restrict__ h,
       float* __restrict__ hnew, __half* __restrict__ pre,
       __half* __restrict__ acat,
       const float* __restrict__ g, const float* __restrict__ b)
{
    const int row = blockIdx.x;
    const int tid = threadIdx.x;
    const size_t rzb = (size_t)row * 4096;
    const size_t hb  = (size_t)row * FF;

    float4 o[2];
#pragma unroll
    for (int half = 0; half < 2; half++) {
        const int c = (tid + half * 256) * 4;
        const float2 r01 = __half22float2(*(const __half2*)&rz[rzb + c]);
        const float2 r23 = __half22float2(*(const __half2*)&rz[rzb + c + 2]);
        const float2 z01 = __half22float2(*(const __half2*)&rz[rzb + 2048 + c]);
        const float2 z23 = __half22float2(*(const __half2*)&rz[rzb + 2048 + c + 2]);
        const float2 i01 = __half22float2(*(const __half2*)&inn[hb + c]);
        const float2 i23 = __half22float2(*(const __half2*)&inn[hb + c + 2]);
        const float2 n01 = __half22float2(*(const __half2*)&hn[hb + c]);
        const float2 n23 = __half22float2(*(const __half2*)&hn[hb + c + 2]);
        const float4 h4  = *(const float4*)&h[hb + c];
        float4 r;
        {
            const float rr = 1.f / (1.f + expf(-r01.x));
            const float zz = 1.f / (1.f + expf(-z01.x));
            const float nn = tanhf(i01.x + rr * n01.x);
            r.x = (1.f - zz) * nn + zz * h4.x;
        }
        {
            const float rr = 1.f / (1.f + expf(-r01.y));
            const float zz = 1.f / (1.f + expf(-z01.y));
            const float nn = tanhf(i01.y + rr * n01.y);
            r.y = (1.f - zz) * nn + zz * h4.y;
        }
        {
            const float rr = 1.f / (1.f + expf(-r23.x));
            const float zz = 1.f / (1.f + expf(-z23.x));
            const float nn = tanhf(i23.x + rr * n23.x);
            r.z = (1.f - zz) * nn + zz * h4.z;
        }
        {
            const float rr = 1.f / (1.f + expf(-r23.y));
            const float zz = 1.f / (1.f + expf(-z23.y));
            const float nn = tanhf(i23.y + rr * n23.y);
            r.w = (1.f - zz) * nn + zz * h4.w;
        }
        o[half] = r;
        *(float4*)&hnew[hb + c] = r;
        __half2 s0 = __floats2half2_rn(r.x, r.y);
        __half2 s1 = __floats2half2_rn(r.z, r.w);
        __half* ac = acat + (size_t)row * KCAT + DD + c;
        *(__half2*)&ac[0] = s0;
        *(__half2*)&ac[2] = s1;
    }

    float s  = (o[0].x + o[0].y) + (o[0].z + o[0].w) + (o[1].x + o[1].y) + (o[1].z + o[1].w);
    float ss = (o[0].x * o[0].x + o[0].y * o[0].y) + (o[0].z * o[0].z + o[0].w * o[0].w)
             + (o[1].x * o[1].x + o[1].y * o[1].y) + (o[1].z * o[1].z + o[1].w * o[1].w);
#pragma unroll
    for (int off = 16; off; off >>= 1) {
        s  += __shfl_down_sync(0xffffffffu, s, off);
        ss += __shfl_down_sync(0xffffffffu, ss, off);
    }
    __shared__ float rs[8], rss[8];
    __shared__ float s_mean, s_rstd;
    const int warp = tid >> 5, lane = tid & 31;
    if (lane == 0) { rs[warp] = s; rss[warp] = ss; }
    __syncthreads();
    if (warp == 0) {
        float S  = (lane < 8) ? rs[lane]  : 0.f;
        float SQ = (lane < 8) ? rss[lane] : 0.f;
#pragma unroll
        for (int off = 4; off; off >>= 1) {
            S  += __shfl_down_sync(0xffffffffu, S, off);
            SQ += __shfl_down_sync(0xffffffffu, SQ, off);
        }
        if (lane == 0) {
            const float mean = S * (1.f / 2048.f);
            const float var  = SQ * (1.f / 2048.f) - mean * mean;
            s_mean = mean;
            s_rstd = rsqrtf(var + 1e-5f);
        }
    }
    __syncthreads();
    const float mean = s_mean, rstd = s_rstd;

#pragma unroll
    for (int half = 0; half < 2; half++) {
        const int c = (tid + half * 256) * 4;
        const float4 g4 = *(const float4*)&g[c];
        const float4 b4 = *(const float4*)&b[c];
        const float4 r = o[half];
        __half2 h0 = __floats2half2_rn((r.x - mean) * rstd * g4.x + b4.x,
                                       (r.y - mean) * rstd * g4.y + b4.y);
        __half2 h1 = __floats2half2_rn((r.z - mean) * rstd * g4.z + b4.z,
                                       (r.w - mean) * rstd * g4.w + b4.w);
        *(__half2*)&pre[hb + c]     = h0;
        *(__half2*)&pre[hb + c + 2] = h1;
    }
}

// =====================================================================
// Attention (512 thr): one CTA per batch; k at kv+0, v at kv+2176.
// =====================================================================
#define ATT 512
#define DD2 (DD/2)
#define KCAT2 (KCAT/2)
__global__ void __launch_bounds__(ATT)
attn_kernel(const __half* __restrict__ q, const __half* __restrict__ kv,
            const unsigned char* __restrict__ mask,
            __half* __restrict__ acat, float* __restrict__ attn_out)
{
    const int b = blockIdx.x;
    const int tid = threadIdx.x;

    __shared__ float qs[10][65];
    __shared__ float ks[36][65];
    __shared__ float dots[10][37];
    __shared__ float attns[10][37];

    const int i = tid / 36;
    const int j = tid % 36;
    float acc = 0.f;

    for (int d0 = 0; d0 < DD; d0 += 64) {
        if (tid < 320) {
            const int r = tid >> 5, c2 = tid & 31;
            const float2 f = __half22float2(
                *(const __half2*)(q + (size_t)(b * 10 + r) * DD + d0 + c2 * 2));
            qs[r][c2 * 2]     = f.x;
            qs[r][c2 * 2 + 1] = f.y;
        }
        for (int t = tid; t < 1152; t += ATT) {
            const int r = t >> 5, c2 = t & 31;
            const float2 f = __half22float2(
                *(const __half2*)(kv + (size_t)(b * 36 + r) * KV + d0 + c2 * 2));
            ks[r][c2 * 2]     = f.x;
            ks[r][c2 * 2 + 1] = f.y;
        }
        __syncthreads();
        if (tid < 360) {
#pragma unroll 16
            for (int dd = 0; dd < 64; dd++)
                acc += qs[i][dd] * ks[j][dd];
        }
        __syncthreads();
    }
    if (tid < 360) dots[i][j] = acc;
    __syncthreads();

    if (tid < 36) {
        const float scale = rsqrtf(2176.0f);
        const int jj = tid;
        bool m[10];
        float dv[10];
        float mx = -3.402823466e38f;
#pragma unroll
        for (int ii = 0; ii < 10; ii++) {
            m[ii] = (mask[b * 10 + ii] != 0);
            dv[ii] = dots[ii][jj] * scale;
            if (!m[ii]) mx = fmaxf(mx, dv[ii]);
        }
        float e[10], sum = 0.f;
#pragma unroll
        for (int ii = 0; ii < 10; ii++) {
            e[ii] = m[ii] ? 0.f : expf(dv[ii] - mx);
            sum += e[ii];
        }
        const float inv = 1.f / sum;
#pragma unroll
        for (int ii = 0; ii < 10; ii++) {
            const float a = e[ii] * inv;
            attns[ii][jj] = a;
            attn_out[(size_t)(b * 10 + ii) * 36 + jj] = a;
        }
    }
    __syncthreads();

    const __half2* v2 = (const __half2*)kv;
    __half2* u2 = (__half2*)acat;
    for (int d2 = tid; d2 < DD2; d2 += ATT) {
        float2 u[10];
#pragma unroll
        for (int ii = 0; ii < 10; ii++) { u[ii].x = 0.f; u[ii].y = 0.f; }
        for (int jj = 0; jj < 36; jj++) {
            const float2 vv = __half22float2(v2[(size_t)(b * 36 + jj) * KV2 + DD2 + d2]);
#pragma unroll
            for (int ii = 0; ii < 10; ii++) {
                const float a = attns[ii][jj];
                u[ii].x += a * vv.x;
                u[ii].y += a * vv.y;
            }
        }
#pragma unroll
        for (int ii = 0; ii < 10; ii++)
            u2[(size_t)(b * 10 + ii) * KCAT2 + d2] = __floats2half2_rn(u[ii].x, u[ii].y);
    }
}

// =====================================================================
// One-pass prep: h0 (f32), hr shadow (fp16 in g_a), s angle tail (fp16),
// out angle tail (f32). All read cand once.
// =====================================================================
__global__ void __launch_bounds__(256)
prep_all(const float* __restrict__ cand, float* __restrict__ h,
         __half* __restrict__ acat, __half* __restrict__ s,
         float* __restrict__ out)
{
    const size_t idx = (size_t)blockIdx.x * 256 + threadIdx.x;
    if (idx >= (size_t)MROW * DD) return;
    const size_t row = idx / DD;
    const int    c   = (int)(idx % DD);
    const float x = cand[idx];
    if (c < 2048) {
        h[row * (size_t)FF + c] = x;
        acat[row * (size_t)KCAT + DD + c] = __float2half_rn(x);
    } else {
        s[idx]   = __float2half_rn(x);
        out[idx] = x;
    }
}

// =====================================================================
// launch
// =====================================================================
extern "C" void kernel_launch(void* const* d_in, const int* in_sizes, int n_in,
                              void* d_out, int out_size)
{
    const float* cand  = (const float*)d_in[0];
    const float* pano  = (const float*)d_in[1];
    const void*  maskp = d_in[2];
    const float* Wq = (const float*)d_in[3];  const float* bq = (const float*)d_in[4];
    const float* Wk = (const float*)d_in[5];  const float* bk = (const float*)d_in[6];
    const float* Wv = (const float*)d_in[7];  const float* bv = (const float*)d_in[8];
    const float* W_ih = (const float*)d_in[9];  const float* b_ih = (const float*)d_in[10];
    const float* W_hh = (const float*)d_in[11]; const float* b_hh = (const float*)d_in[12];
    const float* W1 = (const float*)d_in[13]; const float* b1 = (const float*)d_in[14];
    const float* W2 = (const float*)d_in[15]; const float* b2 = (const float*)d_in[16];
    const float* ln_in_g = (const float*)d_in[17]; const float* ln_in_b = (const float*)d_in[18];
    const float* ln_sl_g = (const float*)d_in[19]; const float* ln_sl_b = (const float*)d_in[20];
    const float* ln_pr_g = (const float*)d_in[21]; const float* ln_pr_b = (const float*)d_in[22];

    float* out      = (float*)d_out;
    float* out_attn = out + (size_t)MROW * DD;

    __half *p_pano, *p_kv, *p_s, *p_q, *p_a, *p_t1, *p_pre, *p_w;
    __half *p_wih, *p_whh, *p_wrz, *p_rz, *p_inn, *p_hn;
    float *p_h, *p_hnew, *p_brz, *p_bkv;
    unsigned char* p_mask;
    cudaGetSymbolAddress((void**)&p_pano, g_pano_ln);
    cudaGetSymbolAddress((void**)&p_kv,   g_kv);
    cudaGetSymbolAddress((void**)&p_s,    g_s);
    cudaGetSymbolAddress((void**)&p_q,    g_q);
    cudaGetSymbolAddress((void**)&p_a,    g_a);
    cudaGetSymbolAddress((void**)&p_t1,   g_t1);
    cudaGetSymbolAddress((void**)&p_rz,   g_rz);
    cudaGetSymbolAddress((void**)&p_inn,  g_inn);
    cudaGetSymbolAddress((void**)&p_hn,   g_hn);
    cudaGetSymbolAddress((void**)&p_h,    g_h);
    cudaGetSymbolAddress((void**)&p_hnew, g_hnew);
    cudaGetSymbolAddress((void**)&p_pre,  g_pre);
    cudaGetSymbolAddress((void**)&p_w,    g_wh);
    cudaGetSymbolAddress((void**)&p_wih,  g_wih);
    cudaGetSymbolAddress((void**)&p_whh,  g_whh);
    cudaGetSymbolAddress((void**)&p_wrz,  g_wrz);
    cudaGetSymbolAddress((void**)&p_brz,  g_brz);
    cudaGetSymbolAddress((void**)&p_bkv,  g_bkv);
    cudaGetSymbolAddress((void**)&p_mask, g_mask);

    cudaFuncSetAttribute(gemm_fp16, cudaFuncAttributeMaxDynamicSharedMemorySize, GEMM_DSMEM);
    cudaFuncSetAttribute(gemm_gates, cudaFuncAttributeMaxDynamicSharedMemorySize, GEMM_DSMEM);

    __half* rWq = p_w;
    __half* rWkv = rWq + SZ_QKV;
    __half* rW1 = rWkv + 2 * (size_t)SZ_QKV;
    __half* rW2 = rW1 + SZ_W1;
    {
        const size_t n4 = SZ_W5 / 4;
        half_copy_all<<<(unsigned)((n4 + 255) / 256), 256>>>(Wq, Wk, Wv, W1, W2, p_w);
        half_copy1<<<(unsigned)((SZ_NIH / 4 + 255) / 256), 256>>>(W_ih + (size_t)4096 * DD, p_wih, SZ_NIH / 4);
        half_copy1<<<(unsigned)((SZ_NHH / 4 + 255) / 256), 256>>>(W_hh + (size_t)4096 * FF, p_whh, SZ_NHH / 4);
        interleave_rz<<<(unsigned)((SZ_RZ / 4 + 255) / 256), 256>>>(W_ih, W_hh, p_wrz);
        bias_setup<<<(KV + 255) / 256, 256>>>(b_ih, b_hh, bk, bv, p_brz, p_bkv);
    }

    detect_mask<<<1, 256>>>((const unsigned char*)maskp);
    normalize_mask<<<(MROW + 255) / 256, 256>>>(maskp);

    // pano LN
    ln_rows<<<PROW, 256>>>(pano, p_pano, ln_in_g, ln_in_b, pano, DD, DD, DD, DD - FF);

    // fused k|v projection
    {
        dim3 grd(KV / 128, PROW / 128);
        gemm_fp16<<<grd, 128, GEMM_DSMEM>>>(p_pano, rWkv, p_bkv, nullptr, nullptr, p_kv,
                                            PROW, KV, DD, DD, 0, KV, 3);
    }

    // one-pass prep (h0, hr shadow, s angle tail, out angle tail)
    prep_all<<<(unsigned)(((size_t)MROW * DD + 255) / 256), 256>>>(cand, p_h, p_a, p_s, out);

    for (int it = 0; it < 3; it++) {
        ln_rows<<<MROW, 256>>>(p_h, p_s, ln_sl_g, ln_sl_b, nullptr, FF, DD, 0, 0);
        {
            dim3 grd(DD / 128, MROW / 128);
            gemm_fp16<<<grd, 128, GEMM_DSMEM>>>(p_s, rWq, bq, nullptr, nullptr, p_q,
                                                MROW, DD, DD, DD, 0, DD, 3);
        }
        attn_kernel<<<BB, ATT>>>(p_q, p_kv, p_mask, p_a, out_attn);
        {
            dim3 grd(32, MROW / 128, 3);
            gemm_gates<<<grd, 128, GEMM_DSMEM>>>(p_a, p_wrz, p_brz,
                                                 p_wih, b_ih + 4096,
                                                 p_whh, b_hh + 4096,
                                                 p_rz, p_inn, p_hn);
        }
        gru_ln<<<MROW, 256>>>(p_rz, p_inn, p_hn, p_h, p_hnew, p_pre, p_a, ln_pr_g, ln_pr_b);
        {
            dim3 grd(HH / 128, MROW / 128);
            gemm_fp16<<<grd, 128, GEMM_DSMEM>>>(p_pre, rW1, b1, nullptr, nullptr, p_t1,
                                                MROW, HH, FF, FF, 0, HH, 1);
        }
        {
            dim3 grd(FF / 128, MROW / 128);
            float* cf = (it == 2) ? out : p_h;
            int ldc  = (it == 2) ? DD : FF;
            gemm_fp16<<<grd, 128, GEMM_DSMEM>>>(p_t1, rW2, b2, p_hnew, cf, p_a + DD,
                                                MROW, FF, HH, HH, ldc, KCAT, 2);
        }
    }
}

// round 16
// speedup vs baseline: 1.0178x; 1.0178x over previous
#include <cuda_runtime.h>
#include <cuda_fp16.h>
#include <cstdint>
#include <cstddef>

// ---------------- problem constants ----------------
#define BB   1024
#define SS   10
#define NN   36
#define FF   2048
#define DD   2176
#define HH   2176
#define MROW (BB*SS)          // 10240
#define PROW (BB*NN)          // 36864
#define KCAT 4224             // DD + FF
#define KV   4352
#define KV2  (KV/2)

#define SZ_QKV (2176*2176)
#define SZ_W1  (2176*2048)
#define SZ_W2  (2048*2176)
#define SZ_W5  ((size_t)3*SZ_QKV + SZ_W1 + SZ_W2)
#define SZ_RZ  ((size_t)4096*KCAT)
#define SZ_NIH ((size_t)2048*DD)
#define SZ_NHH ((size_t)2048*FF)

// ---------------- scratch (device globals; no allocation allowed) --------
__device__ __half g_pano_ln[(size_t)PROW * DD];
__device__ __half g_kv     [(size_t)PROW * KV];
__device__ __half g_s      [(size_t)MROW * DD];
__device__ __half g_q      [(size_t)MROW * DD];
__device__ __half g_a      [(size_t)MROW * KCAT];   // [upd | hr]
__device__ __half g_t1     [(size_t)MROW * HH];
__device__ __half g_rz     [(size_t)MROW * 4096];
__device__ __half g_inn    [(size_t)MROW * FF];
__device__ __half g_hn     [(size_t)MROW * FF];
__device__ float  g_h      [(size_t)MROW * FF];
__device__ float  g_hnew   [(size_t)MROW * FF];
__device__ __half g_pre    [(size_t)MROW * FF];
__device__ __half g_wh     [SZ_W5];
__device__ __half g_wih    [SZ_NIH];     // W_ih rows 4096:6144
__device__ __half g_whh    [SZ_NHH];     // W_hh rows 4096:6144
__device__ __half g_wrz    [SZ_RZ];
__device__ float  g_brz    [4096];
__device__ float  g_bkv    [KV];
__device__ int            g_mask_mode;
__device__ unsigned char  g_mask[MROW];

// ---------------- helpers ----------------
__device__ __forceinline__ void cp16(void* dst, const void* src) {
    uint32_t d = (uint32_t)__cvta_generic_to_shared(dst);
    asm volatile("cp.async.cg.shared.global [%0], [%1], 16;" :: "r"(d), "l"(src));
}

__device__ __forceinline__ uint32_t smem_u32(const void* p) {
    uint32_t a;
    asm("{ .reg .u64 t; cvta.to.shared.u64 t, %1; cvt.u32.u64 %0, t; }" : "=r"(a) : "l"(p));
    return a;
}

__device__ __forceinline__ void ldsm4(uint32_t& d0, uint32_t& d1, uint32_t& d2,
                                      uint32_t& d3, uint32_t addr) {
    asm volatile("ldmatrix.sync.aligned.m8n8.x4.shared.b16 {%0,%1,%2,%3}, [%4];"
                 : "=r"(d0), "=r"(d1), "=r"(d2), "=r"(d3) : "r"(addr));
}

// =====================================================================
// Mask dtype detection + normalization.
// =====================================================================
__global__ void detect_mask(const unsigned char* __restrict__ m)
{
    __shared__ int has1, has23;
    if (threadIdx.x == 0) { has1 = 0; has23 = 0; }
    __syncthreads();
    for (int i = threadIdx.x; i < MROW; i += 256) {
        if (m[i]) {
            const int p = i & 3;
            if (p == 1) atomicOr(&has1, 1);
            if (p >= 2) atomicOr(&has23, 1);
        }
    }
    __syncthreads();
    if (threadIdx.x == 0)
        g_mask_mode = has1 ? 1 : (has23 ? 2 : 0);
}

__global__ void normalize_mask(const void* __restrict__ m)
{
    const int i = blockIdx.x * 256 + threadIdx.x;
    if (i >= MROW) return;
    const int mode = g_mask_mode;
    unsigned char r;
    if (mode == 1)      r = (((const unsigned char*)m)[i] != 0);
    else if (mode == 2) r = (((const float*)m)[i] != 0.0f);
    else                r = (((const int*)m)[i] != 0);
    g_mask[i] = r;
}

// ---------------- fused fp16 weight copies ----------------
__global__ void __launch_bounds__(256)
half_copy_all(const float* s0, const float* s1, const float* s2,
              const float* s3, const float* s4, __half* __restrict__ d)
{
    const size_t seg_end[5] = {
        (size_t)SZ_QKV, (size_t)2*SZ_QKV, (size_t)3*SZ_QKV,
        (size_t)3*SZ_QKV + SZ_W1, SZ_W5 };
    const float* srcs[5] = { s0, s1, s2, s3, s4 };

    const size_t i4 = (size_t)blockIdx.x * 256 + threadIdx.x;
    const size_t e0 = i4 * 4;
    if (e0 >= SZ_W5) return;

    int seg = 0;
    size_t base = 0;
#pragma unroll
    for (int k = 0; k < 5; k++) {
        if (e0 >= seg_end[k]) { seg = k + 1; base = seg_end[k]; }
    }
    const float4 v = *(const float4*)(srcs[seg] + (e0 - base));
    __half2 h0 = __floats2half2_rn(v.x, v.y);
    __half2 h1 = __floats2half2_rn(v.z, v.w);
    uint2 o; o.x = *(uint32_t*)&h0; o.y = *(uint32_t*)&h1;
    *(uint2*)(d + e0) = o;
}

__global__ void __launch_bounds__(256)
half_copy1(const float* __restrict__ s, __half* __restrict__ d, size_t n4)
{
    const size_t i = (size_t)blockIdx.x * 256 + threadIdx.x;
    if (i >= n4) return;
    const float4 v = ((const float4*)s)[i];
    __half2 h0 = __floats2half2_rn(v.x, v.y);
    __half2 h1 = __floats2half2_rn(v.z, v.w);
    uint2 o; o.x = *(uint32_t*)&h0; o.y = *(uint32_t*)&h1;
    ((uint2*)d)[i] = o;
}

// W_rz[o, 0:2176] = W_ih[o,:]; W_rz[o, 2176:4224] = W_hh[o,:]  (o < 4096)
__global__ void __launch_bounds__(256)
interleave_rz(const float* __restrict__ Wih, const float* __restrict__ Whh,
              __half* __restrict__ d)
{
    const size_t i4 = (size_t)blockIdx.x * 256 + threadIdx.x;
    const size_t e0 = i4 * 4;
    if (e0 >= SZ_RZ) return;
    const int o = (int)(e0 / KCAT);
    const int c = (int)(e0 % KCAT);
    const float* src = (c < DD) ? (Wih + (size_t)o * DD + c)
                                : (Whh + (size_t)o * FF + (c - DD));
    const float4 v = *(const float4*)src;
    __half2 h0 = __floats2half2_rn(v.x, v.y);
    __half2 h1 = __floats2half2_rn(v.z, v.w);
    uint2 ov; ov.x = *(uint32_t*)&h0; ov.y = *(uint32_t*)&h1;
    *(uint2*)(d + e0) = ov;
}

__global__ void __launch_bounds__(256)
bias_setup(const float* __restrict__ bih, const float* __restrict__ bhh,
           const float* __restrict__ bk, const float* __restrict__ bv,
           float* __restrict__ brz, float* __restrict__ bkv)
{
    const int i = blockIdx.x * 256 + threadIdx.x;
    if (i < 4096) brz[i] = bih[i] + bhh[i];
    if (i < KV)   bkv[i] = (i < DD) ? bk[i] : bv[i - DD];
}

// =====================================================================
// FP16 GEMM core (device body): CTA 128x128, 128 thr, 3-stage k64 ring.
// mode 0: Cf(f32,ldC)=acc+bias ; 1: Ch=relu ; 2: Cf=+addm & Ch ; 3: Ch
// =====================================================================
#define STG_BYTES 32768
#define GEMM_DSMEM (3*STG_BYTES + 1024)

__device__ __forceinline__ void load_stage(const __half* __restrict__ A, int ldA,
                                           const __half* __restrict__ W,
                                           int K, int bm0, int bn0, int kt,
                                           char* stg, int tid)
{
    const __half* Asrc = A + (size_t)bm0 * ldA + kt * 64;
    const __half* Wsrc = W + (size_t)bn0 * K + kt * 64;
#pragma unroll
    for (int i = 0; i < 8; i++) {
        const int idx = i * 128 + tid;
        const int row = idx >> 3;
        const int g   = idx & 7;
        const int perm = g ^ (row & 7);
        cp16(stg + row * 128 + perm * 16, Asrc + (size_t)row * ldA + g * 8);
    }
#pragma unroll
    for (int i = 0; i < 8; i++) {
        const int idx = i * 128 + tid;
        const int row = idx >> 3;
        const int g   = idx & 7;
        const int perm = g ^ (row & 7);
        cp16(stg + 16384 + row * 128 + perm * 16, Wsrc + (size_t)row * K + g * 8);
    }
    asm volatile("cp.async.commit_group;" ::: "memory");
}

__device__ __forceinline__ void load_frags(uint32_t stg, const uint32_t* oA,
                                           const uint32_t* oB,
                                           uint32_t a[4][4], uint32_t b[8][2])
{
#pragma unroll
    for (int mi = 0; mi < 4; mi++)
        ldsm4(a[mi][0], a[mi][1], a[mi][2], a[mi][3], stg + oA[mi]);
#pragma unroll
    for (int p = 0; p < 4; p++) {
        uint32_t d0, d1, d2, d3;
        ldsm4(d0, d1, d2, d3, stg + oB[p]);
        b[2 * p][0] = d0;     b[2 * p][1] = d2;
        b[2 * p + 1][0] = d1; b[2 * p + 1][1] = d3;
    }
}

__device__ __forceinline__ void do_mmas(const uint32_t a[4][4], const uint32_t b[8][2],
                                        float acc[4][8][4])
{
#pragma unroll
    for (int nj = 0; nj < 8; nj++) {
#pragma unroll
        for (int mi = 0; mi < 4; mi++) {
            asm volatile(
                "mma.sync.aligned.m16n8k16.row.col.f32.f16.f16.f32 "
                "{%0,%1,%2,%3},{%4,%5,%6,%7},{%8,%9},{%0,%1,%2,%3};\n"
                : "+f"(acc[mi][nj][0]), "+f"(acc[mi][nj][1]),
                  "+f"(acc[mi][nj][2]), "+f"(acc[mi][nj][3])
                : "r"(a[mi][0]), "r"(a[mi][1]), "r"(a[mi][2]), "r"(a[mi][3]),
                  "r"(b[nj][0]), "r"(b[nj][1]));
        }
    }
}

__device__ __forceinline__ void gemm_body(
    const __half* __restrict__ A, const __half* __restrict__ W,
    const float* __restrict__ bias, const float* __restrict__ addm,
    float* __restrict__ Cf, __half* __restrict__ Ch,
    int N, int K, int ldA, int ldC, int ldH, int mode)
{
    extern __shared__ char smraw[];
    char* base = (char*)(((uintptr_t)smraw + 1023) & ~(uintptr_t)1023);
    const uint32_t sb = smem_u32(base);

    const int tid  = threadIdx.x;
    const int lane = tid & 31;
    const int warp = tid >> 5;
    const int wm   = warp >> 1;
    const int wn   = warp & 1;
    const int gid  = lane >> 2;
    const int tg   = lane & 3;
    const int mtx  = lane >> 3;
    const int rowin = lane & 7;

    const int bm0 = blockIdx.y * 128;
    const int bn0 = blockIdx.x * 128;

    uint32_t offA[4][4], offB[4][4];
#pragma unroll
    for (int ks = 0; ks < 4; ks++) {
#pragma unroll
        for (int mi = 0; mi < 4; mi++) {
            const int r = wm * 64 + mi * 16 + (mtx & 1) * 8 + rowin;
            const int g = ks * 2 + (mtx >> 1);
            offA[ks][mi] = (uint32_t)(r * 128 + ((g ^ (r & 7)) << 4));
        }
#pragma unroll
        for (int p = 0; p < 4; p++) {
            const int r = wn * 64 + p * 16 + (mtx & 1) * 8 + rowin;
            const int g = ks * 2 + (mtx >> 1);
            offB[ks][p] = (uint32_t)(16384 + r * 128 + ((g ^ (r & 7)) << 4));
        }
    }

    float acc[4][8][4];
#pragma unroll
    for (int mi = 0; mi < 4; mi++)
#pragma unroll
        for (int nj = 0; nj < 8; nj++)
#pragma unroll
            for (int c = 0; c < 4; c++) acc[mi][nj][c] = 0.f;

    const int nkt = K >> 6;

    load_stage(A, ldA, W, K, bm0, bn0, 0, base,             tid);
    load_stage(A, ldA, W, K, bm0, bn0, 1, base + STG_BYTES, tid);
    asm volatile("cp.async.wait_group 1;" ::: "memory");
    __syncthreads();

    uint32_t fa[2][4][4], fb[2][8][2];
    load_frags(sb, offA[0], offB[0], fa[0], fb[0]);

    int stg_i = 0;
    for (int kt = 0; kt < nkt; kt++) {
        const uint32_t stg = sb + (uint32_t)stg_i * STG_BYTES;
        const int stg_n = (stg_i == 2) ? 0 : stg_i + 1;

        if (kt + 2 < nkt) {
            const int stg_p = (stg_n == 2) ? 0 : stg_n + 1;
            load_stage(A, ldA, W, K, bm0, bn0, kt + 2, base + stg_p * STG_BYTES, tid);
        } else {
            asm volatile("cp.async.commit_group;" ::: "memory");
        }
        load_frags(stg, offA[1], offB[1], fa[1], fb[1]);
        do_mmas(fa[0], fb[0], acc);

        load_frags(stg, offA[2], offB[2], fa[0], fb[0]);
        do_mmas(fa[1], fb[1], acc);

        load_frags(stg, offA[3], offB[3], fa[1], fb[1]);
        do_mmas(fa[0], fb[0], acc);

        asm volatile("cp.async.wait_group 1;" ::: "memory");
        __syncthreads();
        if (kt + 1 < nkt)
            load_frags(sb + (uint32_t)stg_n * STG_BYTES, offA[0], offB[0], fa[0], fb[0]);
        do_mmas(fa[1], fb[1], acc);

        stg_i = stg_n;
    }

    // epilogue
#pragma unroll
    for (int mi = 0; mi < 4; mi++) {
#pragma unroll
        for (int nj = 0; nj < 8; nj++) {
            const int col = bn0 + wn * 64 + nj * 8 + tg * 2;
            const float2 bv = *(const float2*)&bias[col];
#pragma unroll
            for (int ch = 0; ch < 2; ch++) {
                const int row = bm0 + wm * 64 + mi * 16 + gid + ch * 8;
                float x0 = acc[mi][nj][ch * 2 + 0] + bv.x;
                float x1 = acc[mi][nj][ch * 2 + 1] + bv.y;
                if (mode == 0) {
                    float2 o; o.x = x0; o.y = x1;
                    *(float2*)&Cf[(size_t)row * ldC + col] = o;
                } else if (mode == 1) {
                    __half2 hh = __floats2half2_rn(fmaxf(x0, 0.f), fmaxf(x1, 0.f));
                    *(__half2*)&Ch[(size_t)row * ldH + col] = hh;
                } else if (mode == 2) {
                    const float2 av = *(const float2*)&addm[(size_t)row * N + col];
                    x0 += av.x; x1 += av.y;
                    float2 o; o.x = x0; o.y = x1;
                    *(float2*)&Cf[(size_t)row * ldC + col] = o;
                    __half2 hh = __floats2half2_rn(x0, x1);
                    *(__half2*)&Ch[(size_t)row * ldH + col] = hh;
                } else {
                    __half2 hh = __floats2half2_rn(x0, x1);
                    *(__half2*)&Ch[(size_t)row * ldH + col] = hh;
                }
            }
        }
    }
}

__global__ void __launch_bounds__(128, 2)
gemm_fp16(const __half* __restrict__ A, const __half* __restrict__ W,
          const float* __restrict__ bias, const float* __restrict__ addm,
          float* __restrict__ Cf, __half* __restrict__ Ch,
          int M, int N, int K, int ldA, int ldC, int ldH, int mode)
{
    gemm_body(A, W, bias, addm, Cf, Ch, N, K, ldA, ldC, ldH, mode);
}

// Fused gate GEMMs: z=0 -> rz (N=4096,K=4224); z=1 -> inn; z=2 -> hn.
__global__ void __launch_bounds__(128, 2)
gemm_gates(const __half* __restrict__ acat,
           const __half* __restrict__ wrz, const float* __restrict__ brz,
           const __half* __restrict__ wih_n, const float* __restrict__ bih_n,
           const __half* __restrict__ whh_n, const float* __restrict__ bhh_n,
           __half* __restrict__ rz, __half* __restrict__ inn, __half* __restrict__ hn)
{
    const int z = blockIdx.z;
    if (z == 0) {
        gemm_body(acat, wrz, brz, nullptr, nullptr, rz, 4096, KCAT, KCAT, 0, 4096, 3);
    } else if (z == 1) {
        if (blockIdx.x >= 16) return;
        gemm_body(acat, wih_n, bih_n, nullptr, nullptr, inn, FF, DD, KCAT, 0, FF, 3);
    } else {
        if (blockIdx.x >= 16) return;
        gemm_body(acat + DD, whh_n, bhh_n, nullptr, nullptr, hn, FF, FF, KCAT, 0, FF, 3);
    }
}

// =====================================================================
// Row LayerNorm over first 2048 cols + optional tail passthrough.
// =====================================================================
__global__ void __launch_bounds__(256)
ln_rows(const float* __restrict__ in, __half* __restrict__ out,
        const float* __restrict__ g, const float* __restrict__ b,
        const float* __restrict__ tail_src,
        int in_stride, int out_stride, int tail_stride, int tail_len)
{
    const int row = blockIdx.x;
    const int tid = threadIdx.x;
    const float* x = in + (size_t)row * in_stride;

    const float4 va = *(const float4*)&x[tid * 4];
    const float4 vb = *(const float4*)&x[(tid + 256) * 4];

    float s  = (va.x + va.y) + (va.z + va.w) + (vb.x + vb.y) + (vb.z + vb.w);
    float ss = (va.x * va.x + va.y * va.y) + (va.z * va.z + va.w * va.w)
             + (vb.x * vb.x + vb.y * vb.y) + (vb.z * vb.z + vb.w * vb.w);

#pragma unroll
    for (int off = 16; off; off >>= 1) {
        s  += __shfl_down_sync(0xffffffffu, s, off);
        ss += __shfl_down_sync(0xffffffffu, ss, off);
    }
    __shared__ float rs[8], rss[8];
    __shared__ float s_mean, s_rstd;
    const int warp = tid >> 5, lane = tid & 31;
    if (lane == 0) { rs[warp] = s; rss[warp] = ss; }
    __syncthreads();
    if (warp == 0) {
        float S  = (lane < 8) ? rs[lane]  : 0.f;
        float SQ = (lane < 8) ? rss[lane] : 0.f;
#pragma unroll
        for (int off = 4; off; off >>= 1) {
            S  += __shfl_down_sync(0xffffffffu, S, off);
            SQ += __shfl_down_sync(0xffffffffu, SQ, off);
        }
        if (lane == 0) {
            const float mean = S * (1.f / 2048.f);
            const float var  = SQ * (1.f / 2048.f) - mean * mean;
            s_mean = mean;
            s_rstd = rsqrtf(var + 1e-5f);
        }
    }
    __syncthreads();
    const float mean = s_mean, rstd = s_rstd;

    __half* o = out + (size_t)row * out_stride;
    {
        const int c0 = tid * 4;
        const float4 g4 = *(const float4*)&g[c0];
        const float4 b4 = *(const float4*)&b[c0];
        __half2 h0 = __floats2half2_rn((va.x - mean) * rstd * g4.x + b4.x,
                                       (va.y - mean) * rstd * g4.y + b4.y);
        __half2 h1 = __floats2half2_rn((va.z - mean) * rstd * g4.z + b4.z,
                                       (va.w - mean) * rstd * g4.w + b4.w);
        *(__half2*)&o[c0]     = h0;
        *(__half2*)&o[c0 + 2] = h1;
    }
    {
        const int c1 = (tid + 256) * 4;
        const float4 g4 = *(const float4*)&g[c1];
        const float4 b4 = *(const float4*)&b[c1];
        __half2 h0 = __floats2half2_rn((vb.x - mean) * rstd * g4.x + b4.x,
                                       (vb.y - mean) * rstd * g4.y + b4.y);
        __half2 h1 = __floats2half2_rn((vb.z - mean) * rstd * g4.z + b4.z,
                                       (vb.w - mean) * rstd * g4.w + b4.w);
        *(__half2*)&o[c1]     = h0;
        *(__half2*)&o[c1 + 2] = h1;
    }
    if (tail_len) {
        for (int c = tid; c < tail_len; c += 256)
            o[2048 + c] = __float2half_rn(tail_src[(size_t)row * tail_stride + 2048 + c]);
    }
}

// =====================================================================
// Fused GRU + LayerNorm(pre): one CTA per row. Gates fp16.
// =====================================================================
__global__ void __launch_bounds__(256)
gru_ln(const __half* __restrict__ rz, const __half* __restrict__ inn,
       const __half* __restrict__ hn, const float* __restrict__ h,
       float* __restrict__ hnew, __half* __restrict__ pre,
       __half* __restrict__ acat,
       const float* __restrict__ g, const float* __restrict__ b)
{
    const int row = blockIdx.x;
    const int tid = threadIdx.x;
    const size_t rzb = (size_t)row * 4096;
    const size_t hb  = (size_t)row * FF;

    float4 o[2];
#pragma unroll
    for (int half = 0; half < 2; half++) {
        const int c = (tid + half * 256) * 4;
        const float2 r01 = __half22float2(*(const __half2*)&rz[rzb + c]);
        const float2 r23 = __half22float2(*(const __half2*)&rz[rzb + c + 2]);
        const float2 z01 = __half22float2(*(const __half2*)&rz[rzb + 2048 + c]);
        const float2 z23 = __half22float2(*(const __half2*)&rz[rzb + 2048 + c + 2]);
        const float2 i01 = __half22float2(*(const __half2*)&inn[hb + c]);
        const float2 i23 = __half22float2(*(const __half2*)&inn[hb + c + 2]);
        const float2 n01 = __half22float2(*(const __half2*)&hn[hb + c]);
        const float2 n23 = __half22float2(*(const __half2*)&hn[hb + c + 2]);
        const float4 h4  = *(const float4*)&h[hb + c];
        float4 r;
        {
            const float rr = 1.f / (1.f + expf(-r01.x));
            const float zz = 1.f / (1.f + expf(-z01.x));
            const float nn = tanhf(i01.x + rr * n01.x);
            r.x = (1.f - zz) * nn + zz * h4.x;
        }
        {
            const float rr = 1.f / (1.f + expf(-r01.y));
            const float zz = 1.f / (1.f + expf(-z01.y));
            const float nn = tanhf(i01.y + rr * n01.y);
            r.y = (1.f - zz) * nn + zz * h4.y;
        }
        {
            const float rr = 1.f / (1.f + expf(-r23.x));
            const float zz = 1.f / (1.f + expf(-z23.x));
            const float nn = tanhf(i23.x + rr * n23.x);
            r.z = (1.f - zz) * nn + zz * h4.z;
        }
        {
            const float rr = 1.f / (1.f + expf(-r23.y));
            const float zz = 1.f / (1.f + expf(-z23.y));
            const float nn = tanhf(i23.y + rr * n23.y);
            r.w = (1.f - zz) * nn + zz * h4.w;
        }
        o[half] = r;
        *(float4*)&hnew[hb + c] = r;
        __half2 s0 = __floats2half2_rn(r.x, r.y);
        __half2 s1 = __floats2half2_rn(r.z, r.w);
        __half* ac = acat + (size_t)row * KCAT + DD + c;
        *(__half2*)&ac[0] = s0;
        *(__half2*)&ac[2] = s1;
    }

    float s  = (o[0].x + o[0].y) + (o[0].z + o[0].w) + (o[1].x + o[1].y) + (o[1].z + o[1].w);
    float ss = (o[0].x * o[0].x + o[0].y * o[0].y) + (o[0].z * o[0].z + o[0].w * o[0].w)
             + (o[1].x * o[1].x + o[1].y * o[1].y) + (o[1].z * o[1].z + o[1].w * o[1].w);
#pragma unroll
    for (int off = 16; off; off >>= 1) {
        s  += __shfl_down_sync(0xffffffffu, s, off);
        ss += __shfl_down_sync(0xffffffffu, ss, off);
    }
    __shared__ float rs[8], rss[8];
    __shared__ float s_mean, s_rstd;
    const int warp = tid >> 5, lane = tid & 31;
    if (lane == 0) { rs[warp] = s; rss[warp] = ss; }
    __syncthreads();
    if (warp == 0) {
        float S  = (lane < 8) ? rs[lane]  : 0.f;
        float SQ = (lane < 8) ? rss[lane] : 0.f;
#pragma unroll
        for (int off = 4; off; off >>= 1) {
            S  += __shfl_down_sync(0xffffffffu, S, off);
            SQ += __shfl_down_sync(0xffffffffu, SQ, off);
        }
        if (lane == 0) {
            const float mean = S * (1.f / 2048.f);
            const float var  = SQ * (1.f / 2048.f) - mean * mean;
            s_mean = mean;
            s_rstd = rsqrtf(var + 1e-5f);
        }
    }
    __syncthreads();
    const float mean = s_mean, rstd = s_rstd;

#pragma unroll
    for (int half = 0; half < 2; half++) {
        const int c = (tid + half * 256) * 4;
        const float4 g4 = *(const float4*)&g[c];
        const float4 b4 = *(const float4*)&b[c];
        const float4 r = o[half];
        __half2 h0 = __floats2half2_rn((r.x - mean) * rstd * g4.x + b4.x,
                                       (r.y - mean) * rstd * g4.y + b4.y);
        __half2 h1 = __floats2half2_rn((r.z - mean) * rstd * g4.z + b4.z,
                                       (r.w - mean) * rstd * g4.w + b4.w);
        *(__half2*)&pre[hb + c]     = h0;
        *(__half2*)&pre[hb + c + 2] = h1;
    }
}

// =====================================================================
// Attention: one CTA per batch; k at kv+0, v at kv+2176 (ld KV).
// =====================================================================
#define ATT 384
#define DD2 (DD/2)
#define KCAT2 (KCAT/2)
__global__ void __launch_bounds__(ATT)
attn_kernel(const __half* __restrict__ q, const __half* __restrict__ kv,
            const unsigned char* __restrict__ mask,
            __half* __restrict__ acat, float* __restrict__ attn_out)
{
    const int b = blockIdx.x;
    const int tid = threadIdx.x;

    __shared__ float qs[10][65];
    __shared__ float ks[36][65];
    __shared__ float dots[10][37];
    __shared__ float attns[10][37];

    const int i = tid / 36;
    const int j = tid % 36;
    float acc = 0.f;

    for (int d0 = 0; d0 < DD; d0 += 64) {
        for (int t = tid; t < 320; t += ATT) {
            const int r = t >> 5, c2 = t & 31;
            const float2 f = __half22float2(
                *(const __half2*)(q + (size_t)(b * 10 + r) * DD + d0 + c2 * 2));
            qs[r][c2 * 2]     = f.x;
            qs[r][c2 * 2 + 1] = f.y;
        }
        for (int t = tid; t < 1152; t += ATT) {
            const int r = t >> 5, c2 = t & 31;
            const float2 f = __half22float2(
                *(const __half2*)(kv + (size_t)(b * 36 + r) * KV + d0 + c2 * 2));
            ks[r][c2 * 2]     = f.x;
            ks[r][c2 * 2 + 1] = f.y;
        }
        __syncthreads();
        if (tid < 360) {
#pragma unroll 16
            for (int dd = 0; dd < 64; dd++)
                acc += qs[i][dd] * ks[j][dd];
        }
        __syncthreads();
    }
    if (tid < 360) dots[i][j] = acc;
    __syncthreads();

    if (tid < 36) {
        const float scale = rsqrtf(2176.0f);
        const int jj = tid;
        bool m[10];
        float dv[10];
        float mx = -3.402823466e38f;
#pragma unroll
        for (int ii = 0; ii < 10; ii++) {
            m[ii] = (mask[b * 10 + ii] != 0);
            dv[ii] = dots[ii][jj] * scale;
            if (!m[ii]) mx = fmaxf(mx, dv[ii]);
        }
        float e[10], sum = 0.f;
#pragma unroll
        for (int ii = 0; ii < 10; ii++) {
            e[ii] = m[ii] ? 0.f : expf(dv[ii] - mx);
            sum += e[ii];
        }
        const float inv = 1.f / sum;
#pragma unroll
        for (int ii = 0; ii < 10; ii++) {
            const float a = e[ii] * inv;
            attns[ii][jj] = a;
            attn_out[(size_t)(b * 10 + ii) * 36 + jj] = a;
        }
    }
    __syncthreads();

    const __half2* v2 = (const __half2*)kv;
    __half2* u2 = (__half2*)acat;
    for (int d2 = tid; d2 < DD2; d2 += ATT) {
        float2 u[10];
#pragma unroll
        for (int ii = 0; ii < 10; ii++) { u[ii].x = 0.f; u[ii].y = 0.f; }
        for (int jj = 0; jj < 36; jj++) {
            const float2 vv = __half22float2(v2[(size_t)(b * 36 + jj) * KV2 + DD2 + d2]);
#pragma unroll
            for (int ii = 0; ii < 10; ii++) {
                const float a = attns[ii][jj];
                u[ii].x += a * vv.x;
                u[ii].y += a * vv.y;
            }
        }
#pragma unroll
        for (int ii = 0; ii < 10; ii++)
            u2[(size_t)(b * 10 + ii) * KCAT2 + d2] = __floats2half2_rn(u[ii].x, u[ii].y);
    }
}

// ---------------- misc copies ----------------
__global__ void __launch_bounds__(256)
init_h(const float* __restrict__ cand, float* __restrict__ h, __half* __restrict__ acat)
{
    const size_t idx = (size_t)blockIdx.x * 256 + threadIdx.x;
    const size_t row = idx >> 11;
    const size_t f   = idx & 2047;
    const float x = cand[row * (size_t)DD + f];
    h[idx] = x;
    acat[row * (size_t)KCAT + DD + f] = __float2half_rn(x);
}

__global__ void __launch_bounds__(256)
angle_to_s(const float* __restrict__ cand, __half* __restrict__ s)
{
    const int idx = blockIdx.x * 256 + threadIdx.x;
    const int row = idx >> 7;
    const int c   = idx & 127;
    const size_t o = (size_t)row * DD + 2048 + c;
    s[o] = __float2half_rn(cand[o]);
}

__global__ void __launch_bounds__(256)
angle_tail(const float* __restrict__ cand, float* __restrict__ out)
{
    const int idx = blockIdx.x * 256 + threadIdx.x;
    const int row = idx >> 7;
    const int c   = idx & 127;
    const size_t o = (size_t)row * DD + 2048 + c;
    out[o] = cand[o];
}

// =====================================================================
// launch
// =====================================================================
extern "C" void kernel_launch(void* const* d_in, const int* in_sizes, int n_in,
                              void* d_out, int out_size)
{
    const float* cand  = (const float*)d_in[0];
    const float* pano  = (const float*)d_in[1];
    const void*  maskp = d_in[2];
    const float* Wq = (const float*)d_in[3];  const float* bq = (const float*)d_in[4];
    const float* Wk = (const float*)d_in[5];  const float* bk = (const float*)d_in[6];
    const float* Wv = (const float*)d_in[7];  const float* bv = (const float*)d_in[8];
    const float* W_ih = (const float*)d_in[9];  const float* b_ih = (const float*)d_in[10];
    const float* W_hh = (const float*)d_in[11]; const float* b_hh = (const float*)d_in[12];
    const float* W1 = (const float*)d_in[13]; const float* b1 = (const float*)d_in[14];
    const float* W2 = (const float*)d_in[15]; const float* b2 = (const float*)d_in[16];
    const float* ln_in_g = (const float*)d_in[17]; const float* ln_in_b = (const float*)d_in[18];
    const float* ln_sl_g = (const float*)d_in[19]; const float* ln_sl_b = (const float*)d_in[20];
    const float* ln_pr_g = (const float*)d_in[21]; const float* ln_pr_b = (const float*)d_in[22];

    float* out      = (float*)d_out;
    float* out_attn = out + (size_t)MROW * DD;

    __half *p_pano, *p_kv, *p_s, *p_q, *p_a, *p_t1, *p_pre, *p_w;
    __half *p_wih, *p_whh, *p_wrz, *p_rz, *p_inn, *p_hn;
    float *p_h, *p_hnew, *p_brz, *p_bkv;
    unsigned char* p_mask;
    cudaGetSymbolAddress((void**)&p_pano, g_pano_ln);
    cudaGetSymbolAddress((void**)&p_kv,   g_kv);
    cudaGetSymbolAddress((void**)&p_s,    g_s);
    cudaGetSymbolAddress((void**)&p_q,    g_q);
    cudaGetSymbolAddress((void**)&p_a,    g_a);
    cudaGetSymbolAddress((void**)&p_t1,   g_t1);
    cudaGetSymbolAddress((void**)&p_rz,   g_rz);
    cudaGetSymbolAddress((void**)&p_inn,  g_inn);
    cudaGetSymbolAddress((void**)&p_hn,   g_hn);
    cudaGetSymbolAddress((void**)&p_h,    g_h);
    cudaGetSymbolAddress((void**)&p_hnew, g_hnew);
    cudaGetSymbolAddress((void**)&p_pre,  g_pre);
    cudaGetSymbolAddress((void**)&p_w,    g_wh);
    cudaGetSymbolAddress((void**)&p_wih,  g_wih);
    cudaGetSymbolAddress((void**)&p_whh,  g_whh);
    cudaGetSymbolAddress((void**)&p_wrz,  g_wrz);
    cudaGetSymbolAddress((void**)&p_brz,  g_brz);
    cudaGetSymbolAddress((void**)&p_bkv,  g_bkv);
    cudaGetSymbolAddress((void**)&p_mask, g_mask);

    cudaFuncSetAttribute(gemm_fp16, cudaFuncAttributeMaxDynamicSharedMemorySize, GEMM_DSMEM);
    cudaFuncSetAttribute(gemm_gates, cudaFuncAttributeMaxDynamicSharedMemorySize, GEMM_DSMEM);

    // fp16 weight copies (Wk, Wv adjacent -> fused kv weights)
    __half* rWq = p_w;
    __half* rWkv = rWq + SZ_QKV;
    __half* rW1 = rWkv + 2 * (size_t)SZ_QKV;
    __half* rW2 = rW1 + SZ_W1;
    {
        const size_t n4 = SZ_W5 / 4;
        half_copy_all<<<(unsigned)((n4 + 255) / 256), 256>>>(Wq, Wk, Wv, W1, W2, p_w);
        // only rows 4096:6144 of W_ih / W_hh are used (n-gate)
        half_copy1<<<(unsigned)((SZ_NIH / 4 + 255) / 256), 256>>>(W_ih + (size_t)4096 * DD, p_wih, SZ_NIH / 4);
        half_copy1<<<(unsigned)((SZ_NHH / 4 + 255) / 256), 256>>>(W_hh + (size_t)4096 * FF, p_whh, SZ_NHH / 4);
        interleave_rz<<<(unsigned)((SZ_RZ / 4 + 255) / 256), 256>>>(W_ih, W_hh, p_wrz);
        bias_setup<<<(KV + 255) / 256, 256>>>(b_ih, b_hh, bk, bv, p_brz, p_bkv);
    }

    // mask dtype detection + canonicalization
    detect_mask<<<1, 256>>>((const unsigned char*)maskp);
    normalize_mask<<<(MROW + 255) / 256, 256>>>(maskp);

    // pano LN
    ln_rows<<<PROW, 256>>>(pano, p_pano, ln_in_g, ln_in_b, pano, DD, DD, DD, DD - FF);

    // fused k|v projection
    {
        dim3 grd(KV / 128, PROW / 128);
        gemm_fp16<<<grd, 128, GEMM_DSMEM>>>(p_pano, rWkv, p_bkv, nullptr, nullptr, p_kv,
                                            PROW, KV, DD, DD, 0, KV, 3);
    }

    init_h<<<(MROW * FF) / 256, 256>>>(cand, p_h, p_a);
    angle_to_s<<<(MROW * 128) / 256, 256>>>(cand, p_s);

    for (int it = 0; it < 3; it++) {
        ln_rows<<<MROW, 256>>>(p_h, p_s, ln_sl_g, ln_sl_b, nullptr, FF, DD, 0, 0);
        {
            dim3 grd(DD / 128, MROW / 128);
            gemm_fp16<<<grd, 128, GEMM_DSMEM>>>(p_s, rWq, bq, nullptr, nullptr, p_q,
                                                MROW, DD, DD, DD, 0, DD, 3);
        }
        attn_kernel<<<BB, ATT>>>(p_q, p_kv, p_mask, p_a, out_attn);
        {
            // fused rz + inn + hn (z dimension)
            dim3 grd(32, MROW / 128, 3);
            gemm_gates<<<grd, 128, GEMM_DSMEM>>>(p_a, p_wrz, p_brz,
                                                 p_wih, b_ih + 4096,
                                                 p_whh, b_hh + 4096,
                                                 p_rz, p_inn, p_hn);
        }
        gru_ln<<<MROW, 256>>>(p_rz, p_inn, p_hn, p_h, p_hnew, p_pre, p_a, ln_pr_g, ln_pr_b);
        {
            dim3 grd(HH / 128, MROW / 128);
            gemm_fp16<<<grd, 128, GEMM_DSMEM>>>(p_pre, rW1, b1, nullptr, nullptr, p_t1,
                                                MROW, HH, FF, FF, 0, HH, 1);
        }
        {
            dim3 grd(FF / 128, MROW / 128);
            float* cf = (it == 2) ? out : p_h;
            int ldc  = (it == 2) ? DD : FF;
            gemm_fp16<<<grd, 128, GEMM_DSMEM>>>(p_t1, rW2, b2, p_hnew, cf, p_a + DD,
                                                MROW, FF, HH, HH, ldc, KCAT, 2);
        }
    }

    // angle tail of slots output
    angle_tail<<<(MROW * 128) / 256, 256>>>(cand, out);
}

// round 17
// speedup vs baseline: 1.0192x; 1.0015x over previous
#include <cuda_runtime.h>
#include <cuda_fp16.h>
#include <cstdint>
#include <cstddef>

// ---------------- problem constants ----------------
#define BB   1024
#define SS   10
#define NN   36
#define FF   2048
#define DD   2176
#define HH   2176
#define MROW (BB*SS)          // 10240
#define PROW (BB*NN)          // 36864
#define KCAT 4224             // DD + FF
#define KV   4352
#define KV2  (KV/2)

#define SZ_QKV (2176*2176)
#define SZ_W1  (2176*2048)
#define SZ_W2  (2048*2176)
#define SZ_W5  ((size_t)3*SZ_QKV + SZ_W1 + SZ_W2)
#define SZ_RZ  ((size_t)4096*KCAT)
#define SZ_NIH ((size_t)2048*DD)
#define SZ_NHH ((size_t)2048*FF)

// ---------------- scratch (device globals; no allocation allowed) --------
__device__ __half g_pano_ln[(size_t)PROW * DD];
__device__ __half g_kv     [(size_t)PROW * KV];
__device__ __half g_s      [(size_t)MROW * DD];
__device__ __half g_q      [(size_t)MROW * DD];
__device__ __half g_a      [(size_t)MROW * KCAT];   // [upd | hr]
__device__ __half g_t1     [(size_t)MROW * HH];
__device__ __half g_rz     [(size_t)MROW * 4096];
__device__ __half g_inn    [(size_t)MROW * FF];
__device__ __half g_hn     [(size_t)MROW * FF];
__device__ float  g_h      [(size_t)MROW * FF];
__device__ __half g_hnew   [(size_t)MROW * FF];     // fp16 residual
__device__ __half g_pre    [(size_t)MROW * FF];
__device__ __half g_wh     [SZ_W5];
__device__ __half g_wih    [SZ_NIH];     // W_ih rows 4096:6144
__device__ __half g_whh    [SZ_NHH];     // W_hh rows 4096:6144
__device__ __half g_wrz    [SZ_RZ];
__device__ float  g_brz    [4096];
__device__ float  g_bkv    [KV];
__device__ int            g_mask_mode;
__device__ unsigned char  g_mask[MROW];

// ---------------- helpers ----------------
__device__ __forceinline__ void cp16(void* dst, const void* src) {
    uint32_t d = (uint32_t)__cvta_generic_to_shared(dst);
    asm volatile("cp.async.cg.shared.global [%0], [%1], 16;" :: "r"(d), "l"(src));
}

__device__ __forceinline__ uint32_t smem_u32(const void* p) {
    uint32_t a;
    asm("{ .reg .u64 t; cvta.to.shared.u64 t, %1; cvt.u32.u64 %0, t; }" : "=r"(a) : "l"(p));
    return a;
}

__device__ __forceinline__ void ldsm4(uint32_t& d0, uint32_t& d1, uint32_t& d2,
                                      uint32_t& d3, uint32_t addr) {
    asm volatile("ldmatrix.sync.aligned.m8n8.x4.shared.b16 {%0,%1,%2,%3}, [%4];"
                 : "=r"(d0), "=r"(d1), "=r"(d2), "=r"(d3) : "r"(addr));
}

// =====================================================================
// Mask dtype detection + normalization.
// =====================================================================
__global__ void detect_mask(const unsigned char* __restrict__ m)
{
    __shared__ int has1, has23;
    if (threadIdx.x == 0) { has1 = 0; has23 = 0; }
    __syncthreads();
    for (int i = threadIdx.x; i < MROW; i += 256) {
        if (m[i]) {
            const int p = i & 3;
            if (p == 1) atomicOr(&has1, 1);
            if (p >= 2) atomicOr(&has23, 1);
        }
    }
    __syncthreads();
    if (threadIdx.x == 0)
        g_mask_mode = has1 ? 1 : (has23 ? 2 : 0);
}

__global__ void normalize_mask(const void* __restrict__ m)
{
    const int i = blockIdx.x * 256 + threadIdx.x;
    if (i >= MROW) return;
    const int mode = g_mask_mode;
    unsigned char r;
    if (mode == 1)      r = (((const unsigned char*)m)[i] != 0);
    else if (mode == 2) r = (((const float*)m)[i] != 0.0f);
    else                r = (((const int*)m)[i] != 0);
    g_mask[i] = r;
}

// ---------------- fused fp16 weight copies ----------------
__global__ void __launch_bounds__(256)
half_copy_all(const float* s0, const float* s1, const float* s2,
              const float* s3, const float* s4, __half* __restrict__ d)
{
    const size_t seg_end[5] = {
        (size_t)SZ_QKV, (size_t)2*SZ_QKV, (size_t)3*SZ_QKV,
        (size_t)3*SZ_QKV + SZ_W1, SZ_W5 };
    const float* srcs[5] = { s0, s1, s2, s3, s4 };

    const size_t i4 = (size_t)blockIdx.x * 256 + threadIdx.x;
    const size_t e0 = i4 * 4;
    if (e0 >= SZ_W5) return;

    int seg = 0;
    size_t base = 0;
#pragma unroll
    for (int k = 0; k < 5; k++) {
        if (e0 >= seg_end[k]) { seg = k + 1; base = seg_end[k]; }
    }
    const float4 v = *(const float4*)(srcs[seg] + (e0 - base));
    __half2 h0 = __floats2half2_rn(v.x, v.y);
    __half2 h1 = __floats2half2_rn(v.z, v.w);
    uint2 o; o.x = *(uint32_t*)&h0; o.y = *(uint32_t*)&h1;
    *(uint2*)(d + e0) = o;
}

__global__ void __launch_bounds__(256)
half_copy1(const float* __restrict__ s, __half* __restrict__ d, size_t n4)
{
    const size_t i = (size_t)blockIdx.x * 256 + threadIdx.x;
    if (i >= n4) return;
    const float4 v = ((const float4*)s)[i];
    __half2 h0 = __floats2half2_rn(v.x, v.y);
    __half2 h1 = __floats2half2_rn(v.z, v.w);
    uint2 o; o.x = *(uint32_t*)&h0; o.y = *(uint32_t*)&h1;
    ((uint2*)d)[i] = o;
}

// W_rz[o, 0:2176] = W_ih[o,:]; W_rz[o, 2176:4224] = W_hh[o,:]  (o < 4096)
__global__ void __launch_bounds__(256)
interleave_rz(const float* __restrict__ Wih, const float* __restrict__ Whh,
              __half* __restrict__ d)
{
    const size_t i4 = (size_t)blockIdx.x * 256 + threadIdx.x;
    const size_t e0 = i4 * 4;
    if (e0 >= SZ_RZ) return;
    const int o = (int)(e0 / KCAT);
    const int c = (int)(e0 % KCAT);
    const float* src = (c < DD) ? (Wih + (size_t)o * DD + c)
                                : (Whh + (size_t)o * FF + (c - DD));
    const float4 v = *(const float4*)src;
    __half2 h0 = __floats2half2_rn(v.x, v.y);
    __half2 h1 = __floats2half2_rn(v.z, v.w);
    uint2 ov; ov.x = *(uint32_t*)&h0; ov.y = *(uint32_t*)&h1;
    *(uint2*)(d + e0) = ov;
}

__global__ void __launch_bounds__(256)
bias_setup(const float* __restrict__ bih, const float* __restrict__ bhh,
           const float* __restrict__ bk, const float* __restrict__ bv,
           float* __restrict__ brz, float* __restrict__ bkv)
{
    const int i = blockIdx.x * 256 + threadIdx.x;
    if (i < 4096) brz[i] = bih[i] + bhh[i];
    if (i < KV)   bkv[i] = (i < DD) ? bk[i] : bv[i - DD];
}

// =====================================================================
// FP16 GEMM core (device body): CTA 128x128, 128 thr, 3-stage k64 ring.
// mode 0: Cf(f32,ldC)=acc+bias ; 1: Ch=relu ; 2: Cf=+addm(f16) & Ch ; 3: Ch
// =====================================================================
#define STG_BYTES 32768
#define GEMM_DSMEM (3*STG_BYTES + 1024)

__device__ __forceinline__ void load_stage(const __half* __restrict__ A, int ldA,
                                           const __half* __restrict__ W,
                                           int K, int bm0, int bn0, int kt,
                                           char* stg, int tid)
{
    const __half* Asrc = A + (size_t)bm0 * ldA + kt * 64;
    const __half* Wsrc = W + (size_t)bn0 * K + kt * 64;
#pragma unroll
    for (int i = 0; i < 8; i++) {
        const int idx = i * 128 + tid;
        const int row = idx >> 3;
        const int g   = idx & 7;
        const int perm = g ^ (row & 7);
        cp16(stg + row * 128 + perm * 16, Asrc + (size_t)row * ldA + g * 8);
    }
#pragma unroll
    for (int i = 0; i < 8; i++) {
        const int idx = i * 128 + tid;
        const int row = idx >> 3;
        const int g   = idx & 7;
        const int perm = g ^ (row & 7);
        cp16(stg + 16384 + row * 128 + perm * 16, Wsrc + (size_t)row * K + g * 8);
    }
    asm volatile("cp.async.commit_group;" ::: "memory");
}

__device__ __forceinline__ void load_frags(uint32_t stg, const uint32_t* oA,
                                           const uint32_t* oB,
                                           uint32_t a[4][4], uint32_t b[8][2])
{
#pragma unroll
    for (int mi = 0; mi < 4; mi++)
        ldsm4(a[mi][0], a[mi][1], a[mi][2], a[mi][3], stg + oA[mi]);
#pragma unroll
    for (int p = 0; p < 4; p++) {
        uint32_t d0, d1, d2, d3;
        ldsm4(d0, d1, d2, d3, stg + oB[p]);
        b[2 * p][0] = d0;     b[2 * p][1] = d2;
        b[2 * p + 1][0] = d1; b[2 * p + 1][1] = d3;
    }
}

__device__ __forceinline__ void do_mmas(const uint32_t a[4][4], const uint32_t b[8][2],
                                        float acc[4][8][4])
{
#pragma unroll
    for (int nj = 0; nj < 8; nj++) {
#pragma unroll
        for (int mi = 0; mi < 4; mi++) {
            asm volatile(
                "mma.sync.aligned.m16n8k16.row.col.f32.f16.f16.f32 "
                "{%0,%1,%2,%3},{%4,%5,%6,%7},{%8,%9},{%0,%1,%2,%3};\n"
                : "+f"(acc[mi][nj][0]), "+f"(acc[mi][nj][1]),
                  "+f"(acc[mi][nj][2]), "+f"(acc[mi][nj][3])
                : "r"(a[mi][0]), "r"(a[mi][1]), "r"(a[mi][2]), "r"(a[mi][3]),
                  "r"(b[nj][0]), "r"(b[nj][1]));
        }
    }
}

__device__ __forceinline__ void gemm_body(
    const __half* __restrict__ A, const __half* __restrict__ W,
    const float* __restrict__ bias, const __half* __restrict__ addm,
    float* __restrict__ Cf, __half* __restrict__ Ch,
    int N, int K, int ldA, int ldC, int ldH, int mode)
{
    extern __shared__ char smraw[];
    char* base = (char*)(((uintptr_t)smraw + 1023) & ~(uintptr_t)1023);
    const uint32_t sb = smem_u32(base);

    const int tid  = threadIdx.x;
    const int lane = tid & 31;
    const int warp = tid >> 5;
    const int wm   = warp >> 1;
    const int wn   = warp & 1;
    const int gid  = lane >> 2;
    const int tg   = lane & 3;
    const int mtx  = lane >> 3;
    const int rowin = lane & 7;

    const int bm0 = blockIdx.y * 128;
    const int bn0 = blockIdx.x * 128;

    uint32_t offA[4][4], offB[4][4];
#pragma unroll
    for (int ks = 0; ks < 4; ks++) {
#pragma unroll
        for (int mi = 0; mi < 4; mi++) {
            const int r = wm * 64 + mi * 16 + (mtx & 1) * 8 + rowin;
            const int g = ks * 2 + (mtx >> 1);
            offA[ks][mi] = (uint32_t)(r * 128 + ((g ^ (r & 7)) << 4));
        }
#pragma unroll
        for (int p = 0; p < 4; p++) {
            const int r = wn * 64 + p * 16 + (mtx & 1) * 8 + rowin;
            const int g = ks * 2 + (mtx >> 1);
            offB[ks][p] = (uint32_t)(16384 + r * 128 + ((g ^ (r & 7)) << 4));
        }
    }

    float acc[4][8][4];
#pragma unroll
    for (int mi = 0; mi < 4; mi++)
#pragma unroll
        for (int nj = 0; nj < 8; nj++)
#pragma unroll
            for (int c = 0; c < 4; c++) acc[mi][nj][c] = 0.f;

    const int nkt = K >> 6;

    load_stage(A, ldA, W, K, bm0, bn0, 0, base,             tid);
    load_stage(A, ldA, W, K, bm0, bn0, 1, base + STG_BYTES, tid);
    asm volatile("cp.async.wait_group 1;" ::: "memory");
    __syncthreads();

    uint32_t fa[2][4][4], fb[2][8][2];
    load_frags(sb, offA[0], offB[0], fa[0], fb[0]);

    int stg_i = 0;
    for (int kt = 0; kt < nkt; kt++) {
        const uint32_t stg = sb + (uint32_t)stg_i * STG_BYTES;
        const int stg_n = (stg_i == 2) ? 0 : stg_i + 1;

        if (kt + 2 < nkt) {
            const int stg_p = (stg_n == 2) ? 0 : stg_n + 1;
            load_stage(A, ldA, W, K, bm0, bn0, kt + 2, base + stg_p * STG_BYTES, tid);
        } else {
            asm volatile("cp.async.commit_group;" ::: "memory");
        }
        load_frags(stg, offA[1], offB[1], fa[1], fb[1]);
        do_mmas(fa[0], fb[0], acc);

        load_frags(stg, offA[2], offB[2], fa[0], fb[0]);
        do_mmas(fa[1], fb[1], acc);

        load_frags(stg, offA[3], offB[3], fa[1], fb[1]);
        do_mmas(fa[0], fb[0], acc);

        asm volatile("cp.async.wait_group 1;" ::: "memory");
        __syncthreads();
        if (kt + 1 < nkt)
            load_frags(sb + (uint32_t)stg_n * STG_BYTES, offA[0], offB[0], fa[0], fb[0]);
        do_mmas(fa[1], fb[1], acc);

        stg_i = stg_n;
    }

    // epilogue
#pragma unroll
    for (int mi = 0; mi < 4; mi++) {
#pragma unroll
        for (int nj = 0; nj < 8; nj++) {
            const int col = bn0 + wn * 64 + nj * 8 + tg * 2;
            const float2 bv = *(const float2*)&bias[col];
#pragma unroll
            for (int ch = 0; ch < 2; ch++) {
                const int row = bm0 + wm * 64 + mi * 16 + gid + ch * 8;
                float x0 = acc[mi][nj][ch * 2 + 0] + bv.x;
                float x1 = acc[mi][nj][ch * 2 + 1] + bv.y;
                if (mode == 0) {
                    float2 o; o.x = x0; o.y = x1;
                    *(float2*)&Cf[(size_t)row * ldC + col] = o;
                } else if (mode == 1) {
                    __half2 hh = __floats2half2_rn(fmaxf(x0, 0.f), fmaxf(x1, 0.f));
                    *(__half2*)&Ch[(size_t)row * ldH + col] = hh;
                } else if (mode == 2) {
                    const float2 av = __half22float2(
                        *(const __half2*)&addm[(size_t)row * N + col]);
                    x0 += av.x; x1 += av.y;
                    float2 o; o.x = x0; o.y = x1;
                    *(float2*)&Cf[(size_t)row * ldC + col] = o;
                    __half2 hh = __floats2half2_rn(x0, x1);
                    *(__half2*)&Ch[(size_t)row * ldH + col] = hh;
                } else {
                    __half2 hh = __floats2half2_rn(x0, x1);
                    *(__half2*)&Ch[(size_t)row * ldH + col] = hh;
                }
            }
        }
    }
}

__global__ void __launch_bounds__(128, 2)
gemm_fp16(const __half* __restrict__ A, const __half* __restrict__ W,
          const float* __restrict__ bias, const __half* __restrict__ addm,
          float* __restrict__ Cf, __half* __restrict__ Ch,
          int M, int N, int K, int ldA, int ldC, int ldH, int mode)
{
    gemm_body(A, W, bias, addm, Cf, Ch, N, K, ldA, ldC, ldH, mode);
}

// Fused gate GEMMs: z=0 -> rz (N=4096,K=4224); z=1 -> inn; z=2 -> hn.
__global__ void __launch_bounds__(128, 2)
gemm_gates(const __half* __restrict__ acat,
           const __half* __restrict__ wrz, const float* __restrict__ brz,
           const __half* __restrict__ wih_n, const float* __restrict__ bih_n,
           const __half* __restrict__ whh_n, const float* __restrict__ bhh_n,
           __half* __restrict__ rz, __half* __restrict__ inn, __half* __restrict__ hn)
{
    const int z = blockIdx.z;
    if (z == 0) {
        gemm_body(acat, wrz, brz, nullptr, nullptr, rz, 4096, KCAT, KCAT, 0, 4096, 3);
    } else if (z == 1) {
        if (blockIdx.x >= 16) return;
        gemm_body(acat, wih_n, bih_n, nullptr, nullptr, inn, FF, DD, KCAT, 0, FF, 3);
    } else {
        if (blockIdx.x >= 16) return;
        gemm_body(acat + DD, whh_n, bhh_n, nullptr, nullptr, hn, FF, FF, KCAT, 0, FF, 3);
    }
}

// =====================================================================
// Row LayerNorm over first 2048 cols + optional tail passthrough.
// =====================================================================
__global__ void __launch_bounds__(256)
ln_rows(const float* __restrict__ in, __half* __restrict__ out,
        const float* __restrict__ g, const float* __restrict__ b,
        const float* __restrict__ tail_src,
        int in_stride, int out_stride, int tail_stride, int tail_len)
{
    const int row = blockIdx.x;
    const int tid = threadIdx.x;
    const float* x = in + (size_t)row * in_stride;

    const float4 va = *(const float4*)&x[tid * 4];
    const float4 vb = *(const float4*)&x[(tid + 256) * 4];

    float s  = (va.x + va.y) + (va.z + va.w) + (vb.x + vb.y) + (vb.z + vb.w);
    float ss = (va.x * va.x + va.y * va.y) + (va.z * va.z + va.w * va.w)
             + (vb.x * vb.x + vb.y * vb.y) + (vb.z * vb.z + vb.w * vb.w);

#pragma unroll
    for (int off = 16; off; off >>= 1) {
        s  += __shfl_down_sync(0xffffffffu, s, off);
        ss += __shfl_down_sync(0xffffffffu, ss, off);
    }
    __shared__ float rs[8], rss[8];
    __shared__ float s_mean, s_rstd;
    const int warp = tid >> 5, lane = tid & 31;
    if (lane == 0) { rs[warp] = s; rss[warp] = ss; }
    __syncthreads();
    if (warp == 0) {
        float S  = (lane < 8) ? rs[lane]  : 0.f;
        float SQ = (lane < 8) ? rss[lane] : 0.f;
#pragma unroll
        for (int off = 4; off; off >>= 1) {
            S  += __shfl_down_sync(0xffffffffu, S, off);
            SQ += __shfl_down_sync(0xffffffffu, SQ, off);
        }
        if (lane == 0) {
            const float mean = S * (1.f / 2048.f);
            const float var  = SQ * (1.f / 2048.f) - mean * mean;
            s_mean = mean;
            s_rstd = rsqrtf(var + 1e-5f);
        }
    }
    __syncthreads();
    const float mean = s_mean, rstd = s_rstd;

    __half* o = out + (size_t)row * out_stride;
    {
        const int c0 = tid * 4;
        const float4 g4 = *(const float4*)&g[c0];
        const float4 b4 = *(const float4*)&b[c0];
        __half2 h0 = __floats2half2_rn((va.x - mean) * rstd * g4.x + b4.x,
                                       (va.y - mean) * rstd * g4.y + b4.y);
        __half2 h1 = __floats2half2_rn((va.z - mean) * rstd * g4.z + b4.z,
                                       (va.w - mean) * rstd * g4.w + b4.w);
        *(__half2*)&o[c0]     = h0;
        *(__half2*)&o[c0 + 2] = h1;
    }
    {
        const int c1 = (tid + 256) * 4;
        const float4 g4 = *(const float4*)&g[c1];
        const float4 b4 = *(const float4*)&b[c1];
        __half2 h0 = __floats2half2_rn((vb.x - mean) * rstd * g4.x + b4.x,
                                       (vb.y - mean) * rstd * g4.y + b4.y);
        __half2 h1 = __floats2half2_rn((vb.z - mean) * rstd * g4.z + b4.z,
                                       (vb.w - mean) * rstd * g4.w + b4.w);
        *(__half2*)&o[c1]     = h0;
        *(__half2*)&o[c1 + 2] = h1;
    }
    if (tail_len) {
        for (int c = tid; c < tail_len; c += 256)
            o[2048 + c] = __float2half_rn(tail_src[(size_t)row * tail_stride + 2048 + c]);
    }
}

// =====================================================================
// Fused GRU + LayerNorm(pre): one CTA per row. Gates fp16; hnew fp16.
// =====================================================================
__global__ void __launch_bounds__(256)
gru_ln(const __half* __restrict__ rz, const __half* __restrict__ inn,
       const __half* __restrict__ hn, const float* __restrict__ h,
       __half* __restrict__ hnew, __half* __restrict__ pre,
       __half* __restrict__ acat,
       const float* __restrict__ g, const float* __restrict__ b)
{
    const int row = blockIdx.x;
    const int tid = threadIdx.x;
    const size_t rzb = (size_t)row * 4096;
    const size_t hb  = (size_t)row * FF;

    float4 o[2];
#pragma unroll
    for (int half = 0; half < 2; half++) {
        const int c = (tid + half * 256) * 4;
        const float2 r01 = __half22float2(*(const __half2*)&rz[rzb + c]);
        const float2 r23 = __half22float2(*(const __half2*)&rz[rzb + c + 2]);
        const float2 z01 = __half22float2(*(const __half2*)&rz[rzb + 2048 + c]);
        const float2 z23 = __half22float2(*(const __half2*)&rz[rzb + 2048 + c + 2]);
        const float2 i01 = __half22float2(*(const __half2*)&inn[hb + c]);
        const float2 i23 = __half22float2(*(const __half2*)&inn[hb + c + 2]);
        const float2 n01 = __half22float2(*(const __half2*)&hn[hb + c]);
        const float2 n23 = __half22float2(*(const __half2*)&hn[hb + c + 2]);
        const float4 h4  = *(const float4*)&h[hb + c];
        float4 r;
        {
            const float rr = 1.f / (1.f + expf(-r01.x));
            const float zz = 1.f / (1.f + expf(-z01.x));
            const float nn = tanhf(i01.x + rr * n01.x);
            r.x = (1.f - zz) * nn + zz * h4.x;
        }
        {
            const float rr = 1.f / (1.f + expf(-r01.y));
            const float zz = 1.f / (1.f + expf(-z01.y));
            const float nn = tanhf(i01.y + rr * n01.y);
            r.y = (1.f - zz) * nn + zz * h4.y;
        }
        {
            const float rr = 1.f / (1.f + expf(-r23.x));
            const float zz = 1.f / (1.f + expf(-z23.x));
            const float nn = tanhf(i23.x + rr * n23.x);
            r.z = (1.f - zz) * nn + zz * h4.z;
        }
        {
            const float rr = 1.f / (1.f + expf(-r23.y));
            const float zz = 1.f / (1.f + expf(-z23.y));
            const float nn = tanhf(i23.y + rr * n23.y);
            r.w = (1.f - zz) * nn + zz * h4.w;
        }
        o[half] = r;
        __half2 hn0 = __floats2half2_rn(r.x, r.y);
        __half2 hn1 = __floats2half2_rn(r.z, r.w);
        *(__half2*)&hnew[hb + c]     = hn0;
        *(__half2*)&hnew[hb + c + 2] = hn1;
        __half* ac = acat + (size_t)row * KCAT + DD + c;
        *(__half2*)&ac[0] = hn0;
        *(__half2*)&ac[2] = hn1;
    }

    float s  = (o[0].x + o[0].y) + (o[0].z + o[0].w) + (o[1].x + o[1].y) + (o[1].z + o[1].w);
    float ss = (o[0].x * o[0].x + o[0].y * o[0].y) + (o[0].z * o[0].z + o[0].w * o[0].w)
             + (o[1].x * o[1].x + o[1].y * o[1].y) + (o[1].z * o[1].z + o[1].w * o[1].w);
#pragma unroll
    for (int off = 16; off; off >>= 1) {
        s  += __shfl_down_sync(0xffffffffu, s, off);
        ss += __shfl_down_sync(0xffffffffu, ss, off);
    }
    __shared__ float rs[8], rss[8];
    __shared__ float s_mean, s_rstd;
    const int warp = tid >> 5, lane = tid & 31;
    if (lane == 0) { rs[warp] = s; rss[warp] = ss; }
    __syncthreads();
    if (warp == 0) {
        float S  = (lane < 8) ? rs[lane]  : 0.f;
        float SQ = (lane < 8) ? rss[lane] : 0.f;
#pragma unroll
        for (int off = 4; off; off >>= 1) {
            S  += __shfl_down_sync(0xffffffffu, S, off);
            SQ += __shfl_down_sync(0xffffffffu, SQ, off);
        }
        if (lane == 0) {
            const float mean = S * (1.f / 2048.f);
            const float var  = SQ * (1.f / 2048.f) - mean * mean;
            s_mean = mean;
            s_rstd = rsqrtf(var + 1e-5f);
        }
    }
    __syncthreads();
    const float mean = s_mean, rstd = s_rstd;

#pragma unroll
    for (int half = 0; half < 2; half++) {
        const int c = (tid + half * 256) * 4;
        const float4 g4 = *(const float4*)&g[c];
        const float4 b4 = *(const float4*)&b[c];
        const float4 r = o[half];
        __half2 h0 = __floats2half2_rn((r.x - mean) * rstd * g4.x + b4.x,
                                       (r.y - mean) * rstd * g4.y + b4.y);
        __half2 h1 = __floats2half2_rn((r.z - mean) * rstd * g4.z + b4.z,
                                       (r.w - mean) * rstd * g4.w + b4.w);
        *(__half2*)&pre[hb + c]     = h0;
        *(__half2*)&pre[hb + c + 2] = h1;
    }
}

// NOTE: hr shadow in g_a now stores hnew (not the fp32-exact h), but the
// mode-2 GEMM overwrites it with the post-residual h anyway before use.

// =====================================================================
// Attention: one CTA per batch; k at kv+0, v at kv+2176 (ld KV).
// =====================================================================
#define ATT 384
#define DD2 (DD/2)
#define KCAT2 (KCAT/2)
__global__ void __launch_bounds__(ATT)
attn_kernel(const __half* __restrict__ q, const __half* __restrict__ kv,
            const unsigned char* __restrict__ mask,
            __half* __restrict__ acat, float* __restrict__ attn_out)
{
    const int b = blockIdx.x;
    const int tid = threadIdx.x;

    __shared__ float qs[10][65];
    __shared__ float ks[36][65];
    __shared__ float dots[10][37];
    __shared__ float attns[10][37];

    const int i = tid / 36;
    const int j = tid % 36;
    float acc = 0.f;

    for (int d0 = 0; d0 < DD; d0 += 64) {
        for (int t = tid; t < 320; t += ATT) {
            const int r = t >> 5, c2 = t & 31;
            const float2 f = __half22float2(
                *(const __half2*)(q + (size_t)(b * 10 + r) * DD + d0 + c2 * 2));
            qs[r][c2 * 2]     = f.x;
            qs[r][c2 * 2 + 1] = f.y;
        }
        for (int t = tid; t < 1152; t += ATT) {
            const int r = t >> 5, c2 = t & 31;
            const float2 f = __half22float2(
                *(const __half2*)(kv + (size_t)(b * 36 + r) * KV + d0 + c2 * 2));
            ks[r][c2 * 2]     = f.x;
            ks[r][c2 * 2 + 1] = f.y;
        }
        __syncthreads();
        if (tid < 360) {
#pragma unroll 16
            for (int dd = 0; dd < 64; dd++)
                acc += qs[i][dd] * ks[j][dd];
        }
        __syncthreads();
    }
    if (tid < 360) dots[i][j] = acc;
    __syncthreads();

    if (tid < 36) {
        const float scale = rsqrtf(2176.0f);
        const int jj = tid;
        bool m[10];
        float dv[10];
        float mx = -3.402823466e38f;
#pragma unroll
        for (int ii = 0; ii < 10; ii++) {
            m[ii] = (mask[b * 10 + ii] != 0);
            dv[ii] = dots[ii][jj] * scale;
            if (!m[ii]) mx = fmaxf(mx, dv[ii]);
        }
        float e[10], sum = 0.f;
#pragma unroll
        for (int ii = 0; ii < 10; ii++) {
            e[ii] = m[ii] ? 0.f : expf(dv[ii] - mx);
            sum += e[ii];
        }
        const float inv = 1.f / sum;
#pragma unroll
        for (int ii = 0; ii < 10; ii++) {
            const float a = e[ii] * inv;
            attns[ii][jj] = a;
            attn_out[(size_t)(b * 10 + ii) * 36 + jj] = a;
        }
    }
    __syncthreads();

    const __half2* v2 = (const __half2*)kv;
    __half2* u2 = (__half2*)acat;
    for (int d2 = tid; d2 < DD2; d2 += ATT) {
        float2 u[10];
#pragma unroll
        for (int ii = 0; ii < 10; ii++) { u[ii].x = 0.f; u[ii].y = 0.f; }
        for (int jj = 0; jj < 36; jj++) {
            const float2 vv = __half22float2(v2[(size_t)(b * 36 + jj) * KV2 + DD2 + d2]);
#pragma unroll
            for (int ii = 0; ii < 10; ii++) {
                const float a = attns[ii][jj];
                u[ii].x += a * vv.x;
                u[ii].y += a * vv.y;
            }
        }
#pragma unroll
        for (int ii = 0; ii < 10; ii++)
            u2[(size_t)(b * 10 + ii) * KCAT2 + d2] = __floats2half2_rn(u[ii].x, u[ii].y);
    }
}

// ---------------- misc copies ----------------
__global__ void __launch_bounds__(256)
init_h(const float* __restrict__ cand, float* __restrict__ h, __half* __restrict__ acat)
{
    const size_t idx = (size_t)blockIdx.x * 256 + threadIdx.x;
    const size_t row = idx >> 11;
    const size_t f   = idx & 2047;
    const float x = cand[row * (size_t)DD + f];
    h[idx] = x;
    acat[row * (size_t)KCAT + DD + f] = __float2half_rn(x);
}

__global__ void __launch_bounds__(256)
angle_to_s(const float* __restrict__ cand, __half* __restrict__ s)
{
    const int idx = blockIdx.x * 256 + threadIdx.x;
    const int row = idx >> 7;
    const int c   = idx & 127;
    const size_t o = (size_t)row * DD + 2048 + c;
    s[o] = __float2half_rn(cand[o]);
}

__global__ void __launch_bounds__(256)
angle_tail(const float* __restrict__ cand, float* __restrict__ out)
{
    const int idx = blockIdx.x * 256 + threadIdx.x;
    const int row = idx >> 7;
    const int c   = idx & 127;
    const size_t o = (size_t)row * DD + 2048 + c;
    out[o] = cand[o];
}

// =====================================================================
// launch
// =====================================================================
extern "C" void kernel_launch(void* const* d_in, const int* in_sizes, int n_in,
                              void* d_out, int out_size)
{
    const float* cand  = (const float*)d_in[0];
    const float* pano  = (const float*)d_in[1];
    const void*  maskp = d_in[2];
    const float* Wq = (const float*)d_in[3];  const float* bq = (const float*)d_in[4];
    const float* Wk = (const float*)d_in[5];  const float* bk = (const float*)d_in[6];
    const float* Wv = (const float*)d_in[7];  const float* bv = (const float*)d_in[8];
    const float* W_ih = (const float*)d_in[9];  const float* b_ih = (const float*)d_in[10];
    const float* W_hh = (const float*)d_in[11]; const float* b_hh = (const float*)d_in[12];
    const float* W1 = (const float*)d_in[13]; const float* b1 = (const float*)d_in[14];
    const float* W2 = (const float*)d_in[15]; const float* b2 = (const float*)d_in[16];
    const float* ln_in_g = (const float*)d_in[17]; const float* ln_in_b = (const float*)d_in[18];
    const float* ln_sl_g = (const float*)d_in[19]; const float* ln_sl_b = (const float*)d_in[20];
    const float* ln_pr_g = (const float*)d_in[21]; const float* ln_pr_b = (const float*)d_in[22];

    float* out      = (float*)d_out;
    float* out_attn = out + (size_t)MROW * DD;

    __half *p_pano, *p_kv, *p_s, *p_q, *p_a, *p_t1, *p_pre, *p_w;
    __half *p_wih, *p_whh, *p_wrz, *p_rz, *p_inn, *p_hn, *p_hnew;
    float *p_h, *p_brz, *p_bkv;
    unsigned char* p_mask;
    cudaGetSymbolAddress((void**)&p_pano, g_pano_ln);
    cudaGetSymbolAddress((void**)&p_kv,   g_kv);
    cudaGetSymbolAddress((void**)&p_s,    g_s);
    cudaGetSymbolAddress((void**)&p_q,    g_q);
    cudaGetSymbolAddress((void**)&p_a,    g_a);
    cudaGetSymbolAddress((void**)&p_t1,   g_t1);
    cudaGetSymbolAddress((void**)&p_rz,   g_rz);
    cudaGetSymbolAddress((void**)&p_inn,  g_inn);
    cudaGetSymbolAddress((void**)&p_hn,   g_hn);
    cudaGetSymbolAddress((void**)&p_h,    g_h);
    cudaGetSymbolAddress((void**)&p_hnew, g_hnew);
    cudaGetSymbolAddress((void**)&p_pre,  g_pre);
    cudaGetSymbolAddress((void**)&p_w,    g_wh);
    cudaGetSymbolAddress((void**)&p_wih,  g_wih);
    cudaGetSymbolAddress((void**)&p_whh,  g_whh);
    cudaGetSymbolAddress((void**)&p_wrz,  g_wrz);
    cudaGetSymbolAddress((void**)&p_brz,  g_brz);
    cudaGetSymbolAddress((void**)&p_bkv,  g_bkv);
    cudaGetSymbolAddress((void**)&p_mask, g_mask);

    cudaFuncSetAttribute(gemm_fp16, cudaFuncAttributeMaxDynamicSharedMemorySize, GEMM_DSMEM);
    cudaFuncSetAttribute(gemm_gates, cudaFuncAttributeMaxDynamicSharedMemorySize, GEMM_DSMEM);

    // fp16 weight copies (Wk, Wv adjacent -> fused kv weights)
    __half* rWq = p_w;
    __half* rWkv = rWq + SZ_QKV;
    __half* rW1 = rWkv + 2 * (size_t)SZ_QKV;
    __half* rW2 = rW1 + SZ_W1;
    {
        const size_t n4 = SZ_W5 / 4;
        half_copy_all<<<(unsigned)((n4 + 255) / 256), 256>>>(Wq, Wk, Wv, W1, W2, p_w);
        half_copy1<<<(unsigned)((SZ_NIH / 4 + 255) / 256), 256>>>(W_ih + (size_t)4096 * DD, p_wih, SZ_NIH / 4);
        half_copy1<<<(unsigned)((SZ_NHH / 4 + 255) / 256), 256>>>(W_hh + (size_t)4096 * FF, p_whh, SZ_NHH / 4);
        interleave_rz<<<(unsigned)((SZ_RZ / 4 + 255) / 256), 256>>>(W_ih, W_hh, p_wrz);
        bias_setup<<<(KV + 255) / 256, 256>>>(b_ih, b_hh, bk, bv, p_brz, p_bkv);
    }

    // mask dtype detection + canonicalization
    detect_mask<<<1, 256>>>((const unsigned char*)maskp);
    normalize_mask<<<(MROW + 255) / 256, 256>>>(maskp);

    // pano LN
    ln_rows<<<PROW, 256>>>(pano, p_pano, ln_in_g, ln_in_b, pano, DD, DD, DD, DD - FF);

    // fused k|v projection
    {
        dim3 grd(KV / 128, PROW / 128);
        gemm_fp16<<<grd, 128, GEMM_DSMEM>>>(p_pano, rWkv, p_bkv, nullptr, nullptr, p_kv,
                                            PROW, KV, DD, DD, 0, KV, 3);
    }

    init_h<<<(MROW * FF) / 256, 256>>>(cand, p_h, p_a);
    angle_to_s<<<(MROW * 128) / 256, 256>>>(cand, p_s);

    for (int it = 0; it < 3; it++) {
        ln_rows<<<MROW, 256>>>(p_h, p_s, ln_sl_g, ln_sl_b, nullptr, FF, DD, 0, 0);
        {
            dim3 grd(DD / 128, MROW / 128);
            gemm_fp16<<<grd, 128, GEMM_DSMEM>>>(p_s, rWq, bq, nullptr, nullptr, p_q,
                                                MROW, DD, DD, DD, 0, DD, 3);
        }
        attn_kernel<<<BB, ATT>>>(p_q, p_kv, p_mask, p_a, out_attn);
        {
            dim3 grd(32, MROW / 128, 3);
            gemm_gates<<<grd, 128, GEMM_DSMEM>>>(p_a, p_wrz, p_brz,
                                                 p_wih, b_ih + 4096,
                                                 p_whh, b_hh + 4096,
                                                 p_rz, p_inn, p_hn);
        }
        gru_ln<<<MROW, 256>>>(p_rz, p_inn, p_hn, p_h, p_hnew, p_pre, p_a, ln_pr_g, ln_pr_b);
        {
            dim3 grd(HH / 128, MROW / 128);
            gemm_fp16<<<grd, 128, GEMM_DSMEM>>>(p_pre, rW1, b1, nullptr, nullptr, p_t1,
                                                MROW, HH, FF, FF, 0, HH, 1);
        }
        {
            dim3 grd(FF / 128, MROW / 128);
            float* cf = (it == 2) ? out : p_h;
            int ldc  = (it == 2) ? DD : FF;
            gemm_fp16<<<grd, 128, GEMM_DSMEM>>>(p_t1, rW2, b2, p_hnew, cf, p_a + DD,
                                                MROW, FF, HH, HH, ldc, KCAT, 2);
        }
    }

    // angle tail of slots output
    angle_tail<<<(MROW * 128) / 256, 256>>>(cand, out);
}